// round 1
// baseline (speedup 1.0000x reference)
#include <cuda_runtime.h>
#include <cstdint>
#include <math.h>

#define HID    1024
#define INTER  4096
#define NTOK   4096
#define NKEYS  64
#define TOPK   8

// ---------------- scratch (no allocations allowed) ----------------
__device__ __align__(16) static float g_H[(size_t)NTOK * INTER];   // 64 MB
__device__ static int   g_tidx[NTOK * TOPK];
__device__ static float g_tw[NTOK * TOPK];

// ---------------- generic NT GEMM: C[M,N] = A[M,K] @ B[N,K]^T ----------------
// MODE 0: C = A@B0^T
// MODE 1: C = silu(A@B0^T) * (A@B1^T)
// MODE 2: C += A@B0^T
#define GBM 128
#define GBN 64
#define GBK 16
#define GTM 8
#define GTN 4

template<int MODE>
__global__ __launch_bounds__(256, 2)
void gemm_nt(const float* __restrict__ A, const float* __restrict__ B0,
             const float* __restrict__ B1, float* __restrict__ C,
             int M, int N, int K)
{
    __shared__ float As [GBK][GBM];
    __shared__ float Bs0[GBK][GBN];
    __shared__ float Bs1[GBK][GBN];

    const int tid = threadIdx.x;
    const int tx  = tid & 15;        // n-dir
    const int ty  = tid >> 4;        // m-dir
    const int row0 = blockIdx.x * GBM;
    const int col0 = blockIdx.y * GBN;

    float acc0[GTM][GTN];
    float acc1[GTM][GTN];
    #pragma unroll
    for (int i = 0; i < GTM; i++)
        #pragma unroll
        for (int j = 0; j < GTN; j++) { acc0[i][j] = 0.f; if (MODE == 1) acc1[i][j] = 0.f; }

    const int nkt = K / GBK;
    for (int kt = 0; kt < nkt; kt++) {
        // load A tile: 128x16 = 512 float4, 2 per thread, store transposed
        #pragma unroll
        for (int l = 0; l < 2; l++) {
            int f  = tid * 2 + l;
            int r  = f >> 2;
            int c4 = f & 3;
            float4 v = *(const float4*)(A + (size_t)(row0 + r) * K + kt * GBK + c4 * 4);
            As[c4*4+0][r] = v.x; As[c4*4+1][r] = v.y;
            As[c4*4+2][r] = v.z; As[c4*4+3][r] = v.w;
        }
        // load B tiles: 64x16 = 256 float4, 1 per thread
        {
            int r  = tid >> 2;
            int c4 = tid & 3;
            float4 v = *(const float4*)(B0 + (size_t)(col0 + r) * K + kt * GBK + c4 * 4);
            Bs0[c4*4+0][r] = v.x; Bs0[c4*4+1][r] = v.y;
            Bs0[c4*4+2][r] = v.z; Bs0[c4*4+3][r] = v.w;
            if (MODE == 1) {
                float4 u = *(const float4*)(B1 + (size_t)(col0 + r) * K + kt * GBK + c4 * 4);
                Bs1[c4*4+0][r] = u.x; Bs1[c4*4+1][r] = u.y;
                Bs1[c4*4+2][r] = u.z; Bs1[c4*4+3][r] = u.w;
            }
        }
        __syncthreads();

        #pragma unroll
        for (int k = 0; k < GBK; k++) {
            float regM[GTM], regN0[GTN], regN1[GTN];
            #pragma unroll
            for (int i = 0; i < GTM; i++) regM[i] = As[k][ty * GTM + i];
            #pragma unroll
            for (int j = 0; j < GTN; j++) regN0[j] = Bs0[k][tx * GTN + j];
            if (MODE == 1) {
                #pragma unroll
                for (int j = 0; j < GTN; j++) regN1[j] = Bs1[k][tx * GTN + j];
            }
            #pragma unroll
            for (int i = 0; i < GTM; i++)
                #pragma unroll
                for (int j = 0; j < GTN; j++) {
                    acc0[i][j] = fmaf(regM[i], regN0[j], acc0[i][j]);
                    if (MODE == 1) acc1[i][j] = fmaf(regM[i], regN1[j], acc1[i][j]);
                }
        }
        __syncthreads();
    }

    #pragma unroll
    for (int i = 0; i < GTM; i++) {
        int r = row0 + ty * GTM + i;
        #pragma unroll
        for (int j = 0; j < GTN; j++) {
            int c = col0 + tx * GTN + j;
            float* p = C + (size_t)r * N + c;
            if (MODE == 0) {
                *p = acc0[i][j];
            } else if (MODE == 1) {
                float a = acc0[i][j];
                float s = a / (1.f + expf(-a));   // silu
                *p = s * acc1[i][j];
            } else {
                *p += acc0[i][j];
            }
        }
    }
}

// ---------------- routing: per logical row m, top8(x) x top8(y) -> top8 sums ----------------
__device__ __forceinline__ void top8_insert(float v, int idx, float* hv, int* hi) {
    if (v <= hv[7]) return;              // strict > : earlier index wins ties
    int p = 7;
    #pragma unroll
    for (int q = 7; q > 0; q--) {
        if (v > hv[q-1]) { hv[q] = hv[q-1]; hi[q] = hi[q-1]; p = q - 1; }
    }
    hv[p] = v; hi[p] = idx;
}

__global__ void routing_kernel(const float* __restrict__ logits /* [NTOK][128] */)
{
    int m = blockIdx.x * blockDim.x + threadIdx.x;
    if (m >= NTOK) return;

    const float* px = logits + (size_t)(m >> 1) * 128 + (m & 1) * 64;          // batch 0
    const float* py = logits + (size_t)(2048 + (m >> 1)) * 128 + (m & 1) * 64; // batch 1

    float vx[8], vy[8];
    int   ix[8], iy[8];
    #pragma unroll
    for (int t = 0; t < 8; t++) { vx[t] = -3.4e38f; vy[t] = -3.4e38f; ix[t] = 0; iy[t] = 0; }
    for (int k = 0; k < NKEYS; k++) top8_insert(px[k], k, vx, ix);
    for (int k = 0; k < NKEYS; k++) top8_insert(py[k], k, vy, iy);

    // top-8 of the 64 candidate sums; iterate a-major (ascending flattened pos)
    float sv[8]; int sa[8];
    #pragma unroll
    for (int t = 0; t < 8; t++) { sv[t] = -3.4e38f; sa[t] = 0; }
    for (int a = 0; a < 8; a++)
        for (int b = 0; b < 8; b++)
            top8_insert(vx[a] + vy[b], a * 8 + b, sv, sa);

    // softmax + renorm (renorm matches reference's norm_topk_prob)
    float mx = sv[0];
    float e[8], s = 0.f;
    #pragma unroll
    for (int t = 0; t < 8; t++) { e[t] = expf(sv[t] - mx); s += e[t]; }
    float w[8], s2 = 0.f;
    #pragma unroll
    for (int t = 0; t < 8; t++) { w[t] = e[t] / s; s2 += w[t]; }
    #pragma unroll
    for (int t = 0; t < 8; t++) w[t] /= s2;

    #pragma unroll
    for (int t = 0; t < 8; t++) {
        int a = sa[t] >> 3, b = sa[t] & 7;
        g_tidx[m * TOPK + t] = ix[a] * NKEYS + iy[b];
        g_tw[m * TOPK + t]   = w[t];
    }
}

// ---------------- experts: out[m] = sum_k silu(de[idx]·x) * w_k * ue[idx] ----------------
__global__ __launch_bounds__(256)
void experts_kernel(const float* __restrict__ X,
                    const float* __restrict__ down_e,
                    const float* __restrict__ up_e,
                    float* __restrict__ out)
{
    __shared__ float4 xs4[HID / 4];
    __shared__ float  ews[TOPK];

    const int m   = blockIdx.x;
    const int tid = threadIdx.x;

    xs4[tid] = ((const float4*)(X + (size_t)m * HID))[tid];
    __syncthreads();

    const float* xs = (const float*)xs4;
    const int wid  = tid >> 5;
    const int lane = tid & 31;

    // 8 warps, one expert dot each
    {
        int e = g_tidx[m * TOPK + wid];
        const float* d = down_e + (size_t)e * HID;
        float s = 0.f;
        for (int k = lane; k < HID; k += 32) s = fmaf(d[k], xs[k], s);
        #pragma unroll
        for (int o = 16; o; o >>= 1) s += __shfl_xor_sync(0xffffffffu, s, o);
        if (lane == 0) {
            float sig = s / (1.f + expf(-s));
            ews[wid] = sig * g_tw[m * TOPK + wid];
        }
    }
    __syncthreads();

    float4 acc = make_float4(0.f, 0.f, 0.f, 0.f);
    #pragma unroll
    for (int k = 0; k < TOPK; k++) {
        int e = g_tidx[m * TOPK + k];
        float w = ews[k];
        float4 u = ((const float4*)(up_e + (size_t)e * HID))[tid];
        acc.x = fmaf(w, u.x, acc.x);
        acc.y = fmaf(w, u.y, acc.y);
        acc.z = fmaf(w, u.z, acc.z);
        acc.w = fmaf(w, u.w, acc.w);
    }
    ((float4*)(out + (size_t)m * HID))[tid] = acc;
}

// ---------------- launch ----------------
extern "C" void kernel_launch(void* const* d_in, const int* in_sizes, int n_in,
                              void* d_out, int out_size)
{
    const float* X        = (const float*)d_in[0]; // hidden_states [2,2048,1024]
    const float* w_gate   = (const float*)d_in[1]; // [4096,1024]
    const float* w_up     = (const float*)d_in[2]; // [4096,1024]
    const float* w_down   = (const float*)d_in[3]; // [1024,4096]
    const float* w_router = (const float*)d_in[4]; // [128,1024]
    const float* down_e   = (const float*)d_in[5]; // [4096,1024]
    const float* up_e     = (const float*)d_in[6]; // [4096,1024]

    float* out    = (float*)d_out;                       // [4096,1024]
    float* logits = (float*)d_out + (size_t)NTOK * HID;  // [4096,128]

    float* Hbuf = nullptr;
    cudaGetSymbolAddress((void**)&Hbuf, g_H);

    // 1) router logits -> d_out logits region (layout == flat (2,n,64))
    {
        dim3 grid(NTOK / GBM, 128 / GBN);
        gemm_nt<0><<<grid, 256>>>(X, w_router, nullptr, logits, NTOK, 128, HID);
    }
    // 2) routing top-k
    routing_kernel<<<NTOK / 256, 256>>>(logits);
    // 3) expert states -> out (initializes it)
    experts_kernel<<<NTOK, 256>>>(X, down_e, up_e, out);
    // 4) H = silu(X@Wg^T) * (X@Wu^T)
    {
        dim3 grid(NTOK / GBM, INTER / GBN);
        gemm_nt<1><<<grid, 256>>>(X, w_gate, w_up, Hbuf, NTOK, INTER, HID);
    }
    // 5) out += H @ Wd^T
    {
        dim3 grid(NTOK / GBM, HID / GBN);
        gemm_nt<2><<<grid, 256>>>(Hbuf, w_down, nullptr, out, NTOK, HID, INTER);
    }
    (void)in_sizes; (void)n_in; (void)out_size;
}

// round 3
// speedup vs baseline: 1.8601x; 1.8601x over previous
#include <cuda_runtime.h>
#include <cstdint>
#include <math.h>

#define HID    1024
#define INTER  4096
#define NTOK   4096
#define NKEYS  64
#define TOPK   8

typedef unsigned short u16;
typedef unsigned int   u32;

// ---------------- scratch (no allocations allowed) ----------------
__device__ __align__(16) static u16   g_Xh[(size_t)NTOK * HID];
__device__ __align__(16) static u16   g_Xl[(size_t)NTOK * HID];
__device__ __align__(16) static u16   g_Wgh[(size_t)INTER * HID];
__device__ __align__(16) static u16   g_Wgl[(size_t)INTER * HID];
__device__ __align__(16) static u16   g_Wuh[(size_t)INTER * HID];
__device__ __align__(16) static u16   g_Wul[(size_t)INTER * HID];
__device__ __align__(16) static u16   g_Wdh[(size_t)HID * INTER];
__device__ __align__(16) static u16   g_Wdl[(size_t)HID * INTER];
__device__ __align__(16) static u16   g_Wrh[(size_t)128 * HID];
__device__ __align__(16) static u16   g_Wrl[(size_t)128 * HID];
__device__ __align__(16) static u16   g_Hh[(size_t)NTOK * INTER];
__device__ __align__(16) static u16   g_Hl[(size_t)NTOK * INTER];
__device__ __align__(16) static float g_G[(size_t)NTOK * INTER];
__device__ static int   g_tidx[NTOK * TOPK];
__device__ static float g_tw[NTOK * TOPK];

// ---------------- helpers ----------------
__device__ __forceinline__ u32 smem_u32(const void* p) {
    u32 a;
    asm("{ .reg .u64 t; cvta.to.shared.u64 t, %1; cvt.u32.u64 %0, t; }" : "=r"(a) : "l"(p));
    return a;
}

__device__ __forceinline__ u32 pack_bf16x2(float hi, float lo) {
    u32 r;
    asm("cvt.rn.bf16x2.f32 %0, %1, %2;" : "=r"(r) : "f"(hi), "f"(lo));
    return r;
}

__device__ __forceinline__ void cp16(u32 dst, const void* src) {
    asm volatile("cp.async.cg.shared.global [%0], [%1], 16;" :: "r"(dst), "l"(src));
}
#define CP_COMMIT() asm volatile("cp.async.commit_group;" ::: "memory")
#define CP_WAIT(n)  asm volatile("cp.async.wait_group %0;" :: "n"(n) : "memory")

__device__ __forceinline__ void mma16816(float* c, const u32* a, const u32* b) {
    asm volatile(
        "mma.sync.aligned.m16n8k16.row.col.f32.bf16.bf16.f32 "
        "{%0,%1,%2,%3}, {%4,%5,%6,%7}, {%8,%9}, {%0,%1,%2,%3};"
        : "+f"(c[0]), "+f"(c[1]), "+f"(c[2]), "+f"(c[3])
        : "r"(a[0]), "r"(a[1]), "r"(a[2]), "r"(a[3]), "r"(b[0]), "r"(b[1]));
}

__device__ __forceinline__ float silu(float x) { return x / (1.f + expf(-x)); }

// ---------------- fp32 -> (bf16 hi, bf16 lo) split ----------------
__global__ void split_kernel(const float* __restrict__ src,
                             u16* __restrict__ hi, u16* __restrict__ lo, int n4)
{
    int i = blockIdx.x * blockDim.x + threadIdx.x;
    if (i >= n4) return;
    float4 v = ((const float4*)src)[i];
    u32 h0 = pack_bf16x2(v.y, v.x);
    u32 h1 = pack_bf16x2(v.w, v.z);
    float rx = v.x - __uint_as_float(h0 << 16);
    float ry = v.y - __uint_as_float(h0 & 0xffff0000u);
    float rz = v.z - __uint_as_float(h1 << 16);
    float rw = v.w - __uint_as_float(h1 & 0xffff0000u);
    u32 l0 = pack_bf16x2(ry, rx);
    u32 l1 = pack_bf16x2(rw, rz);
    ((uint2*)hi)[i] = make_uint2(h0, h1);
    ((uint2*)lo)[i] = make_uint2(l0, l1);
}

// =====================================================================
// HMMA GEMM: C[M,N] = A[M,K] @ B[N,K]^T using bf16x3 split planes.
// CTA tile 128x128, BK=32, 8 warps (warp tile 64x32), cp.async dbuf.
// MODE 0: C = P                (store fp32, for router / gate)
// MODE 1: H = silu(G)*P        (read Gin, write split bf16 to Hh/Hl)
// MODE 2: C += P               (accumulate onto experts output)
// =====================================================================
#define PITCH 80                      // bytes per smem row (32 bf16 + pad)
#define PLANE 10240                   // 128 * 80
#define STAGEB 40960                  // 4 planes

template<int MODE>
__global__ __launch_bounds__(256, 1)
void hgemm(const u16* __restrict__ A_h, const u16* __restrict__ A_l,
           const u16* __restrict__ B_h, const u16* __restrict__ B_l,
           int K, float* __restrict__ C, int ldC,
           const float* __restrict__ Gin,
           u16* __restrict__ Hh, u16* __restrict__ Hl)
{
    extern __shared__ char sm[];
    const u32 sb = smem_u32(sm);
    const int tid  = threadIdx.x;
    const int lane = tid & 31;
    const int wid  = tid >> 5;
    const int row0 = blockIdx.x * 128;
    const int col0 = blockIdx.y * 128;
    const int warpM = (wid >> 2) * 64;
    const int warpN = (wid & 3) * 32;

    // per-thread global/smem load mapping: 2 chunks of 16B
    const int f  = tid * 2;
    const int lr = f >> 2;                 // row within tile (same for both chunks)
    const int c0 = f & 3;                  // chunk index (0 or 2), second = c0+1

    const int NS = K >> 5;

    // issue loads for stage kt into buffer buf
    auto load_stage = [&](int kt, int buf) {
        const size_t goA = (size_t)(row0 + lr) * K + kt * 32;
        const size_t goB = (size_t)(col0 + lr) * K + kt * 32;
        const u32 so = sb + buf * STAGEB + lr * PITCH;
        cp16(so + 0 * PLANE + c0 * 16,       A_h + goA + c0 * 8);
        cp16(so + 0 * PLANE + (c0 + 1) * 16, A_h + goA + (c0 + 1) * 8);
        cp16(so + 1 * PLANE + c0 * 16,       A_l + goA + c0 * 8);
        cp16(so + 1 * PLANE + (c0 + 1) * 16, A_l + goA + (c0 + 1) * 8);
        cp16(so + 2 * PLANE + c0 * 16,       B_h + goB + c0 * 8);
        cp16(so + 2 * PLANE + (c0 + 1) * 16, B_h + goB + (c0 + 1) * 8);
        cp16(so + 3 * PLANE + c0 * 16,       B_l + goB + c0 * 8);
        cp16(so + 3 * PLANE + (c0 + 1) * 16, B_l + goB + (c0 + 1) * 8);
    };

    float acc[4][4][4];
    #pragma unroll
    for (int i = 0; i < 4; i++)
        #pragma unroll
        for (int j = 0; j < 4; j++)
            #pragma unroll
            for (int t = 0; t < 4; t++) acc[i][j][t] = 0.f;

    load_stage(0, 0);
    CP_COMMIT();

    // per-lane fragment smem byte offsets (relative to plane base)
    const int aoff = (lane >> 2) * PITCH + (lane & 3) * 4;   // row(lane/4), k-word(lane%4)
    const int boff = aoff;                                   // same pattern for B

    for (int s = 0; s < NS; s++) {
        const int buf = s & 1;
        if (s + 1 < NS) load_stage(s + 1, buf ^ 1);
        CP_COMMIT();
        CP_WAIT(1);
        __syncthreads();

        const char* stg = sm + buf * STAGEB;
        const char* pAh = stg;
        const char* pAl = stg + PLANE;
        const char* pBh = stg + 2 * PLANE;
        const char* pBl = stg + 3 * PLANE;

        #pragma unroll
        for (int ks = 0; ks < 2; ks++) {
            const int kb = ks * 32;   // 16 bf16 = 32 bytes
            u32 ah[4][4], al[4][4], bh[4][2], bl[4][2];
            #pragma unroll
            for (int i = 0; i < 4; i++) {
                const char* p = pAh + (warpM + i * 16) * PITCH + kb + aoff;
                ah[i][0] = *(const u32*)(p);
                ah[i][1] = *(const u32*)(p + 8 * PITCH);
                ah[i][2] = *(const u32*)(p + 16);
                ah[i][3] = *(const u32*)(p + 8 * PITCH + 16);
                const char* q = pAl + (warpM + i * 16) * PITCH + kb + aoff;
                al[i][0] = *(const u32*)(q);
                al[i][1] = *(const u32*)(q + 8 * PITCH);
                al[i][2] = *(const u32*)(q + 16);
                al[i][3] = *(const u32*)(q + 8 * PITCH + 16);
            }
            #pragma unroll
            for (int j = 0; j < 4; j++) {
                const char* p = pBh + (warpN + j * 8) * PITCH + kb + boff;
                bh[j][0] = *(const u32*)(p);
                bh[j][1] = *(const u32*)(p + 16);
                const char* q = pBl + (warpN + j * 8) * PITCH + kb + boff;
                bl[j][0] = *(const u32*)(q);
                bl[j][1] = *(const u32*)(q + 16);
            }
            #pragma unroll
            for (int i = 0; i < 4; i++)
                #pragma unroll
                for (int j = 0; j < 4; j++) mma16816(acc[i][j], ah[i], bh[j]);
            #pragma unroll
            for (int i = 0; i < 4; i++)
                #pragma unroll
                for (int j = 0; j < 4; j++) mma16816(acc[i][j], ah[i], bl[j]);
            #pragma unroll
            for (int i = 0; i < 4; i++)
                #pragma unroll
                for (int j = 0; j < 4; j++) mma16816(acc[i][j], al[i], bh[j]);
        }
        __syncthreads();
    }

    // ---------------- epilogue ----------------
    #pragma unroll
    for (int i = 0; i < 4; i++) {
        #pragma unroll
        for (int j = 0; j < 4; j++) {
            const int r = row0 + warpM + i * 16 + (lane >> 2);
            const int c = col0 + warpN + j * 8 + (lane & 3) * 2;
            #pragma unroll
            for (int half = 0; half < 2; half++) {
                const int rr = r + half * 8;
                const float v0 = acc[i][j][half * 2 + 0];
                const float v1 = acc[i][j][half * 2 + 1];
                if (MODE == 0) {
                    *(float2*)(C + (size_t)rr * ldC + c) = make_float2(v0, v1);
                } else if (MODE == 1) {
                    float2 g = *(const float2*)(Gin + (size_t)rr * ldC + c);
                    float h0 = silu(g.x) * v0;
                    float h1 = silu(g.y) * v1;
                    u32 hi = pack_bf16x2(h1, h0);
                    float r0 = h0 - __uint_as_float(hi << 16);
                    float r1 = h1 - __uint_as_float(hi & 0xffff0000u);
                    u32 lo = pack_bf16x2(r1, r0);
                    const size_t idx2 = ((size_t)rr * ldC + c) >> 1;
                    ((u32*)Hh)[idx2] = hi;
                    ((u32*)Hl)[idx2] = lo;
                } else {
                    float2 prev = *(const float2*)(C + (size_t)rr * ldC + c);
                    *(float2*)(C + (size_t)rr * ldC + c) =
                        make_float2(prev.x + v0, prev.y + v1);
                }
            }
        }
    }
}

// ---------------- routing: per logical row m, top8(x) x top8(y) -> top8 sums ----------------
__device__ __forceinline__ void top8_insert(float v, int idx, float* hv, int* hi) {
    if (v <= hv[7]) return;              // strict > : earlier index wins ties
    int p = 7;
    #pragma unroll
    for (int q = 7; q > 0; q--) {
        if (v > hv[q-1]) { hv[q] = hv[q-1]; hi[q] = hi[q-1]; p = q - 1; }
    }
    hv[p] = v; hi[p] = idx;
}

__global__ void routing_kernel(const float* __restrict__ logits /* [NTOK][128] */)
{
    int m = blockIdx.x * blockDim.x + threadIdx.x;
    if (m >= NTOK) return;

    const float* px = logits + (size_t)(m >> 1) * 128 + (m & 1) * 64;          // batch 0
    const float* py = logits + (size_t)(2048 + (m >> 1)) * 128 + (m & 1) * 64; // batch 1

    float vx[8], vy[8];
    int   ix[8], iy[8];
    #pragma unroll
    for (int t = 0; t < 8; t++) { vx[t] = -3.4e38f; vy[t] = -3.4e38f; ix[t] = 0; iy[t] = 0; }
    for (int k = 0; k < NKEYS; k++) top8_insert(px[k], k, vx, ix);
    for (int k = 0; k < NKEYS; k++) top8_insert(py[k], k, vy, iy);

    float sv[8]; int sa[8];
    #pragma unroll
    for (int t = 0; t < 8; t++) { sv[t] = -3.4e38f; sa[t] = 0; }
    for (int a = 0; a < 8; a++)
        for (int b = 0; b < 8; b++)
            top8_insert(vx[a] + vy[b], a * 8 + b, sv, sa);

    float mx = sv[0];
    float e[8], s = 0.f;
    #pragma unroll
    for (int t = 0; t < 8; t++) { e[t] = expf(sv[t] - mx); s += e[t]; }
    float w[8], s2 = 0.f;
    #pragma unroll
    for (int t = 0; t < 8; t++) { w[t] = e[t] / s; s2 += w[t]; }
    #pragma unroll
    for (int t = 0; t < 8; t++) w[t] /= s2;

    #pragma unroll
    for (int t = 0; t < 8; t++) {
        int a = sa[t] >> 3, b = sa[t] & 7;
        g_tidx[m * TOPK + t] = ix[a] * NKEYS + iy[b];
        g_tw[m * TOPK + t]   = w[t];
    }
}

// ---------------- experts: out[m] = sum_k silu(de[idx]·x) * w_k * ue[idx] ----------------
__global__ __launch_bounds__(256)
void experts_kernel(const float* __restrict__ X,
                    const float* __restrict__ down_e,
                    const float* __restrict__ up_e,
                    float* __restrict__ out)
{
    __shared__ float4 xs4[HID / 4];
    __shared__ float  ews[TOPK];

    const int m   = blockIdx.x;
    const int tid = threadIdx.x;

    xs4[tid] = ((const float4*)(X + (size_t)m * HID))[tid];
    __syncthreads();

    const float* xs = (const float*)xs4;
    const int wid  = tid >> 5;
    const int lane = tid & 31;

    {
        int e = g_tidx[m * TOPK + wid];
        const float* d = down_e + (size_t)e * HID;
        float s = 0.f;
        for (int k = lane; k < HID; k += 32) s = fmaf(d[k], xs[k], s);
        #pragma unroll
        for (int o = 16; o; o >>= 1) s += __shfl_xor_sync(0xffffffffu, s, o);
        if (lane == 0) {
            float sig = s / (1.f + expf(-s));
            ews[wid] = sig * g_tw[m * TOPK + wid];
        }
    }
    __syncthreads();

    float4 acc = make_float4(0.f, 0.f, 0.f, 0.f);
    #pragma unroll
    for (int k = 0; k < TOPK; k++) {
        int e = g_tidx[m * TOPK + k];
        float w = ews[k];
        float4 u = ((const float4*)(up_e + (size_t)e * HID))[tid];
        acc.x = fmaf(w, u.x, acc.x);
        acc.y = fmaf(w, u.y, acc.y);
        acc.z = fmaf(w, u.z, acc.z);
        acc.w = fmaf(w, u.w, acc.w);
    }
    ((float4*)(out + (size_t)m * HID))[tid] = acc;
}

// ---------------- launch ----------------
static void* sym(const void* s) { void* p = nullptr; cudaGetSymbolAddress(&p, s); return p; }

extern "C" void kernel_launch(void* const* d_in, const int* in_sizes, int n_in,
                              void* d_out, int out_size)
{
    const float* X        = (const float*)d_in[0]; // [2,2048,1024]
    const float* w_gate   = (const float*)d_in[1]; // [4096,1024]
    const float* w_up     = (const float*)d_in[2]; // [4096,1024]
    const float* w_down   = (const float*)d_in[3]; // [1024,4096]
    const float* w_router = (const float*)d_in[4]; // [128,1024]
    const float* down_e   = (const float*)d_in[5]; // [4096,1024]
    const float* up_e     = (const float*)d_in[6]; // [4096,1024]

    float* out    = (float*)d_out;                       // [4096,1024]
    float* logits = (float*)d_out + (size_t)NTOK * HID;  // [4096,128]

    u16 *Xh = (u16*)sym(g_Xh),  *Xl = (u16*)sym(g_Xl);
    u16 *Wgh = (u16*)sym(g_Wgh), *Wgl = (u16*)sym(g_Wgl);
    u16 *Wuh = (u16*)sym(g_Wuh), *Wul = (u16*)sym(g_Wul);
    u16 *Wdh = (u16*)sym(g_Wdh), *Wdl = (u16*)sym(g_Wdl);
    u16 *Wrh = (u16*)sym(g_Wrh), *Wrl = (u16*)sym(g_Wrl);
    u16 *Hh = (u16*)sym(g_Hh),  *Hl = (u16*)sym(g_Hl);
    float* G = (float*)sym(g_G);

    const int SMEM = 2 * STAGEB;   // 81920
    cudaFuncSetAttribute(hgemm<0>, cudaFuncAttributeMaxDynamicSharedMemorySize, SMEM);
    cudaFuncSetAttribute(hgemm<1>, cudaFuncAttributeMaxDynamicSharedMemorySize, SMEM);
    cudaFuncSetAttribute(hgemm<2>, cudaFuncAttributeMaxDynamicSharedMemorySize, SMEM);

    // 0) split fp32 -> bf16 hi/lo planes
    {
        int n4;
        n4 = NTOK * HID / 4;   split_kernel<<<(n4 + 255) / 256, 256>>>(X, Xh, Xl, n4);
        n4 = INTER * HID / 4;  split_kernel<<<(n4 + 255) / 256, 256>>>(w_gate, Wgh, Wgl, n4);
        n4 = INTER * HID / 4;  split_kernel<<<(n4 + 255) / 256, 256>>>(w_up, Wuh, Wul, n4);
        n4 = HID * INTER / 4;  split_kernel<<<(n4 + 255) / 256, 256>>>(w_down, Wdh, Wdl, n4);
        n4 = 128 * HID / 4;    split_kernel<<<(n4 + 255) / 256, 256>>>(w_router, Wrh, Wrl, n4);
    }
    // 1) router logits (layout == flat (2,n,64))
    hgemm<0><<<dim3(NTOK / 128, 1), 256, SMEM>>>(Xh, Xl, Wrh, Wrl, HID,
                                                 logits, 128, nullptr, nullptr, nullptr);
    // 2) routing top-k
    routing_kernel<<<NTOK / 256, 256>>>(logits);
    // 3) expert states -> out (initializes it)
    experts_kernel<<<NTOK, 256>>>(X, down_e, up_e, out);
    // 4) G = X@Wg^T
    hgemm<0><<<dim3(NTOK / 128, INTER / 128), 256, SMEM>>>(Xh, Xl, Wgh, Wgl, HID,
                                                           G, INTER, nullptr, nullptr, nullptr);
    // 5) H = silu(G) * (X@Wu^T), written as split bf16 planes
    hgemm<1><<<dim3(NTOK / 128, INTER / 128), 256, SMEM>>>(Xh, Xl, Wuh, Wul, HID,
                                                           nullptr, INTER, G, Hh, Hl);
    // 6) out += H @ Wd^T
    hgemm<2><<<dim3(NTOK / 128, HID / 128), 256, SMEM>>>(Hh, Hl, Wdh, Wdl, INTER,
                                                         out, HID, nullptr, nullptr, nullptr);
    (void)in_sizes; (void)n_in; (void)out_size;
}

// round 4
// speedup vs baseline: 1.9481x; 1.0473x over previous
#include <cuda_runtime.h>
#include <cuda_fp16.h>
#include <cstdint>
#include <math.h>

#define HID    1024
#define INTER  4096
#define NTOK   4096
#define NKEYS  64
#define TOPK   8

typedef unsigned short u16;
typedef unsigned int   u32;

// ---------------- scratch (no allocations allowed) ----------------
__device__ __align__(16) static u16   g_Xh[(size_t)NTOK * HID];
__device__ __align__(16) static u16   g_Xl[(size_t)NTOK * HID];
__device__ __align__(16) static u16   g_Wgh[(size_t)INTER * HID];
__device__ __align__(16) static u16   g_Wgl[(size_t)INTER * HID];
__device__ __align__(16) static u16   g_Wuh[(size_t)INTER * HID];
__device__ __align__(16) static u16   g_Wul[(size_t)INTER * HID];
__device__ __align__(16) static u16   g_Wdh[(size_t)HID * INTER];
__device__ __align__(16) static u16   g_Wdl[(size_t)HID * INTER];
__device__ __align__(16) static u16   g_Wrh[(size_t)128 * HID];
__device__ __align__(16) static u16   g_Wrl[(size_t)128 * HID];
__device__ __align__(16) static u16   g_Hh[(size_t)NTOK * INTER];
__device__ __align__(16) static u16   g_Hl[(size_t)NTOK * INTER];
__device__ __align__(16) static float g_G[(size_t)NTOK * INTER];
__device__ static int   g_tidx[NTOK * TOPK];
__device__ static float g_tw[NTOK * TOPK];

// ---------------- helpers ----------------
__device__ __forceinline__ u32 smem_u32(const void* p) {
    u32 a;
    asm("{ .reg .u64 t; cvta.to.shared.u64 t, %1; cvt.u32.u64 %0, t; }" : "=r"(a) : "l"(p));
    return a;
}

__device__ __forceinline__ void cp16(u32 dst, const void* src) {
    asm volatile("cp.async.cg.shared.global [%0], [%1], 16;" :: "r"(dst), "l"(src));
}
#define CP_COMMIT() asm volatile("cp.async.commit_group;" ::: "memory")
#define CP_WAIT(n)  asm volatile("cp.async.wait_group %0;" :: "n"(n) : "memory")

__device__ __forceinline__ void ldsm_x4(u32& r0, u32& r1, u32& r2, u32& r3, u32 addr) {
    asm volatile("ldmatrix.sync.aligned.m8n8.x4.shared.b16 {%0,%1,%2,%3}, [%4];"
                 : "=r"(r0), "=r"(r1), "=r"(r2), "=r"(r3) : "r"(addr));
}
__device__ __forceinline__ void ldsm_x2(u32& r0, u32& r1, u32 addr) {
    asm volatile("ldmatrix.sync.aligned.m8n8.x2.shared.b16 {%0,%1}, [%2];"
                 : "=r"(r0), "=r"(r1) : "r"(addr));
}

__device__ __forceinline__ void mma_f32(float* c, const u32* a, const u32* b) {
    asm volatile(
        "mma.sync.aligned.m16n8k16.row.col.f32.f16.f16.f32 "
        "{%0,%1,%2,%3}, {%4,%5,%6,%7}, {%8,%9}, {%0,%1,%2,%3};"
        : "+f"(c[0]), "+f"(c[1]), "+f"(c[2]), "+f"(c[3])
        : "r"(a[0]), "r"(a[1]), "r"(a[2]), "r"(a[3]), "r"(b[0]), "r"(b[1]));
}
__device__ __forceinline__ void mma_f16(u32* c, const u32* a, const u32* b) {
    asm volatile(
        "mma.sync.aligned.m16n8k16.row.col.f16.f16.f16.f16 "
        "{%0,%1}, {%2,%3,%4,%5}, {%6,%7}, {%0,%1};"
        : "+r"(c[0]), "+r"(c[1])
        : "r"(a[0]), "r"(a[1]), "r"(a[2]), "r"(a[3]), "r"(b[0]), "r"(b[1]));
}

__device__ __forceinline__ float silu(float x) { return x / (1.f + expf(-x)); }

// ---------------- fp32 -> (fp16 hi, fp16 lo) split ----------------
__global__ void split_kernel(const float* __restrict__ src,
                             u16* __restrict__ hi, u16* __restrict__ lo, int n4)
{
    int i = blockIdx.x * blockDim.x + threadIdx.x;
    if (i >= n4) return;
    float4 v = ((const float4*)src)[i];
    __half hx = __float2half_rn(v.x), hy = __float2half_rn(v.y);
    __half hz = __float2half_rn(v.z), hw = __float2half_rn(v.w);
    __half lx = __float2half_rn(v.x - __half2float(hx));
    __half ly = __float2half_rn(v.y - __half2float(hy));
    __half lz = __float2half_rn(v.z - __half2float(hz));
    __half lw = __float2half_rn(v.w - __half2float(hw));
    __half2 h0 = __halves2half2(hx, hy), h1 = __halves2half2(hz, hw);
    __half2 l0 = __halves2half2(lx, ly), l1 = __halves2half2(lz, lw);
    ((uint2*)hi)[i] = make_uint2(*(u32*)&h0, *(u32*)&h1);
    ((uint2*)lo)[i] = make_uint2(*(u32*)&l0, *(u32*)&l1);
}

// =====================================================================
// HMMA GEMM: C[M,N] = A[M,K] @ B[N,K]^T with fp16x3 split.
//   hi*hi -> fp32 accum;  hi*lo + lo*hi -> fp16 accum (added at epilogue)
// CTA tile 128x128, BK=32, 8 warps (warp tile 64x32), 3-stage cp.async.
// MODE 0: C = P ; MODE 1: H = silu(G)*P -> split planes ; MODE 2: C += P
// =====================================================================
#define PITCH 80
#define PLANE 10240                   // 128 * 80
#define STAGEB 40960                  // 4 planes

template<int MODE>
__global__ __launch_bounds__(256, 1)
void hgemm(const u16* __restrict__ A_h, const u16* __restrict__ A_l,
           const u16* __restrict__ B_h, const u16* __restrict__ B_l,
           int K, float* __restrict__ C, int ldC,
           const float* __restrict__ Gin,
           u16* __restrict__ Hh, u16* __restrict__ Hl)
{
    extern __shared__ char sm[];
    const u32 sb = smem_u32(sm);
    const int tid  = threadIdx.x;
    const int lane = tid & 31;
    const int wid  = tid >> 5;
    const int row0 = blockIdx.x * 128;
    const int col0 = blockIdx.y * 128;
    const int warpM = (wid >> 2) * 64;
    const int warpN = (wid & 3) * 32;

    // cp.async mapping: 2x16B chunks per plane per thread
    const int f  = tid * 2;
    const int lr = f >> 2;
    const int c0 = f & 3;

    const int NS = K >> 5;

    auto load_stage = [&](int kt, int buf) {
        const size_t goA = (size_t)(row0 + lr) * K + kt * 32;
        const size_t goB = (size_t)(col0 + lr) * K + kt * 32;
        const u32 so = sb + buf * STAGEB + lr * PITCH;
        cp16(so + 0 * PLANE + c0 * 16,       A_h + goA + c0 * 8);
        cp16(so + 0 * PLANE + (c0 + 1) * 16, A_h + goA + (c0 + 1) * 8);
        cp16(so + 1 * PLANE + c0 * 16,       A_l + goA + c0 * 8);
        cp16(so + 1 * PLANE + (c0 + 1) * 16, A_l + goA + (c0 + 1) * 8);
        cp16(so + 2 * PLANE + c0 * 16,       B_h + goB + c0 * 8);
        cp16(so + 2 * PLANE + (c0 + 1) * 16, B_h + goB + (c0 + 1) * 8);
        cp16(so + 3 * PLANE + c0 * 16,       B_l + goB + c0 * 8);
        cp16(so + 3 * PLANE + (c0 + 1) * 16, B_l + goB + (c0 + 1) * 8);
    };

    float acc[4][4][4];
    u32   accX[4][4][2];
    #pragma unroll
    for (int i = 0; i < 4; i++)
        #pragma unroll
        for (int j = 0; j < 4; j++) {
            #pragma unroll
            for (int t = 0; t < 4; t++) acc[i][j][t] = 0.f;
            accX[i][j][0] = 0u; accX[i][j][1] = 0u;
        }

    // ldmatrix per-lane offsets
    const int l4 = lane & 15;
    const u32 aRowOff = (u32)((lane & 15) * PITCH + ((lane >> 4) << 4));
    const u32 bRowOff = (u32)((l4 & 7) * PITCH + ((l4 >> 3) << 4));

    load_stage(0, 0); CP_COMMIT();
    load_stage(1, 1); CP_COMMIT();

    for (int s = 0; s < NS; s++) {
        const int buf = s % 3;
        CP_WAIT(1);
        __syncthreads();
        if (s + 2 < NS) load_stage(s + 2, (s + 2) % 3);
        CP_COMMIT();

        const u32 stg = sb + buf * STAGEB;
        #pragma unroll
        for (int ks = 0; ks < 2; ks++) {
            const u32 kb = ks * 32;
            u32 ah[4][4], al[4][4], bh[4][2], bl[4][2];
            #pragma unroll
            for (int i = 0; i < 4; i++) {
                const u32 ra = stg + (warpM + i * 16) * PITCH + kb + aRowOff;
                ldsm_x4(ah[i][0], ah[i][1], ah[i][2], ah[i][3], ra);
                ldsm_x4(al[i][0], al[i][1], al[i][2], al[i][3], ra + PLANE);
            }
            #pragma unroll
            for (int j = 0; j < 4; j++) {
                const u32 rb = stg + 2 * PLANE + (warpN + j * 8) * PITCH + kb + bRowOff;
                ldsm_x2(bh[j][0], bh[j][1], rb);
                ldsm_x2(bl[j][0], bl[j][1], rb + PLANE);
            }
            #pragma unroll
            for (int i = 0; i < 4; i++)
                #pragma unroll
                for (int j = 0; j < 4; j++) mma_f32(acc[i][j], ah[i], bh[j]);
            #pragma unroll
            for (int i = 0; i < 4; i++)
                #pragma unroll
                for (int j = 0; j < 4; j++) {
                    mma_f16(accX[i][j], ah[i], bl[j]);
                    mma_f16(accX[i][j], al[i], bh[j]);
                }
        }
    }

    // ---------------- epilogue ----------------
    #pragma unroll
    for (int i = 0; i < 4; i++) {
        #pragma unroll
        for (int j = 0; j < 4; j++) {
            float2 x0 = __half22float2(*(__half2*)&accX[i][j][0]);
            float2 x1 = __half22float2(*(__half2*)&accX[i][j][1]);
            const float vv[4] = { acc[i][j][0] + x0.x, acc[i][j][1] + x0.y,
                                  acc[i][j][2] + x1.x, acc[i][j][3] + x1.y };
            const int r = row0 + warpM + i * 16 + (lane >> 2);
            const int c = col0 + warpN + j * 8 + (lane & 3) * 2;
            #pragma unroll
            for (int half = 0; half < 2; half++) {
                const int rr = r + half * 8;
                const float v0 = vv[half * 2 + 0];
                const float v1 = vv[half * 2 + 1];
                if (MODE == 0) {
                    *(float2*)(C + (size_t)rr * ldC + c) = make_float2(v0, v1);
                } else if (MODE == 1) {
                    float2 g = *(const float2*)(Gin + (size_t)rr * ldC + c);
                    float h0 = silu(g.x) * v0;
                    float h1 = silu(g.y) * v1;
                    __half hh0 = __float2half_rn(h0), hh1 = __float2half_rn(h1);
                    __half ll0 = __float2half_rn(h0 - __half2float(hh0));
                    __half ll1 = __float2half_rn(h1 - __half2float(hh1));
                    __half2 hp = __halves2half2(hh0, hh1);
                    __half2 lp = __halves2half2(ll0, ll1);
                    const size_t idx2 = ((size_t)rr * ldC + c) >> 1;
                    ((u32*)Hh)[idx2] = *(u32*)&hp;
                    ((u32*)Hl)[idx2] = *(u32*)&lp;
                } else {
                    float2 prev = *(const float2*)(C + (size_t)rr * ldC + c);
                    *(float2*)(C + (size_t)rr * ldC + c) =
                        make_float2(prev.x + v0, prev.y + v1);
                }
            }
        }
    }
}

// ---------------- routing ----------------
__device__ __forceinline__ void top8_insert(float v, int idx, float* hv, int* hi) {
    if (v <= hv[7]) return;
    int p = 7;
    #pragma unroll
    for (int q = 7; q > 0; q--) {
        if (v > hv[q-1]) { hv[q] = hv[q-1]; hi[q] = hi[q-1]; p = q - 1; }
    }
    hv[p] = v; hi[p] = idx;
}

__global__ void routing_kernel(const float* __restrict__ logits)
{
    int m = blockIdx.x * blockDim.x + threadIdx.x;
    if (m >= NTOK) return;

    const float* px = logits + (size_t)(m >> 1) * 128 + (m & 1) * 64;
    const float* py = logits + (size_t)(2048 + (m >> 1)) * 128 + (m & 1) * 64;

    float vx[8], vy[8];
    int   ix[8], iy[8];
    #pragma unroll
    for (int t = 0; t < 8; t++) { vx[t] = -3.4e38f; vy[t] = -3.4e38f; ix[t] = 0; iy[t] = 0; }
    for (int k = 0; k < NKEYS; k++) top8_insert(px[k], k, vx, ix);
    for (int k = 0; k < NKEYS; k++) top8_insert(py[k], k, vy, iy);

    float sv[8]; int sa[8];
    #pragma unroll
    for (int t = 0; t < 8; t++) { sv[t] = -3.4e38f; sa[t] = 0; }
    for (int a = 0; a < 8; a++)
        for (int b = 0; b < 8; b++)
            top8_insert(vx[a] + vy[b], a * 8 + b, sv, sa);

    float mx = sv[0];
    float e[8], s = 0.f;
    #pragma unroll
    for (int t = 0; t < 8; t++) { e[t] = expf(sv[t] - mx); s += e[t]; }
    float w[8], s2 = 0.f;
    #pragma unroll
    for (int t = 0; t < 8; t++) { w[t] = e[t] / s; s2 += w[t]; }
    #pragma unroll
    for (int t = 0; t < 8; t++) w[t] /= s2;

    #pragma unroll
    for (int t = 0; t < 8; t++) {
        int a = sa[t] >> 3, b = sa[t] & 7;
        g_tidx[m * TOPK + t] = ix[a] * NKEYS + iy[b];
        g_tw[m * TOPK + t]   = w[t];
    }
}

// ---------------- experts ----------------
__global__ __launch_bounds__(256)
void experts_kernel(const float* __restrict__ X,
                    const float* __restrict__ down_e,
                    const float* __restrict__ up_e,
                    float* __restrict__ out)
{
    __shared__ float4 xs4[HID / 4];
    __shared__ float  ews[TOPK];

    const int m   = blockIdx.x;
    const int tid = threadIdx.x;

    xs4[tid] = ((const float4*)(X + (size_t)m * HID))[tid];
    __syncthreads();

    const float* xs = (const float*)xs4;
    const int wid  = tid >> 5;
    const int lane = tid & 31;

    {
        int e = g_tidx[m * TOPK + wid];
        const float* d = down_e + (size_t)e * HID;
        float s = 0.f;
        for (int k = lane; k < HID; k += 32) s = fmaf(d[k], xs[k], s);
        #pragma unroll
        for (int o = 16; o; o >>= 1) s += __shfl_xor_sync(0xffffffffu, s, o);
        if (lane == 0) {
            float sig = s / (1.f + expf(-s));
            ews[wid] = sig * g_tw[m * TOPK + wid];
        }
    }
    __syncthreads();

    float4 acc = make_float4(0.f, 0.f, 0.f, 0.f);
    #pragma unroll
    for (int k = 0; k < TOPK; k++) {
        int e = g_tidx[m * TOPK + k];
        float w = ews[k];
        float4 u = ((const float4*)(up_e + (size_t)e * HID))[tid];
        acc.x = fmaf(w, u.x, acc.x);
        acc.y = fmaf(w, u.y, acc.y);
        acc.z = fmaf(w, u.z, acc.z);
        acc.w = fmaf(w, u.w, acc.w);
    }
    ((float4*)(out + (size_t)m * HID))[tid] = acc;
}

// ---------------- launch ----------------
static void* sym(const void* s) { void* p = nullptr; cudaGetSymbolAddress(&p, s); return p; }

extern "C" void kernel_launch(void* const* d_in, const int* in_sizes, int n_in,
                              void* d_out, int out_size)
{
    const float* X        = (const float*)d_in[0];
    const float* w_gate   = (const float*)d_in[1];
    const float* w_up     = (const float*)d_in[2];
    const float* w_down   = (const float*)d_in[3];
    const float* w_router = (const float*)d_in[4];
    const float* down_e   = (const float*)d_in[5];
    const float* up_e     = (const float*)d_in[6];

    float* out    = (float*)d_out;
    float* logits = (float*)d_out + (size_t)NTOK * HID;

    u16 *Xh = (u16*)sym(g_Xh),  *Xl = (u16*)sym(g_Xl);
    u16 *Wgh = (u16*)sym(g_Wgh), *Wgl = (u16*)sym(g_Wgl);
    u16 *Wuh = (u16*)sym(g_Wuh), *Wul = (u16*)sym(g_Wul);
    u16 *Wdh = (u16*)sym(g_Wdh), *Wdl = (u16*)sym(g_Wdl);
    u16 *Wrh = (u16*)sym(g_Wrh), *Wrl = (u16*)sym(g_Wrl);
    u16 *Hh = (u16*)sym(g_Hh),  *Hl = (u16*)sym(g_Hl);
    float* G = (float*)sym(g_G);

    const int SMEM = 3 * STAGEB;   // 122880
    cudaFuncSetAttribute(hgemm<0>, cudaFuncAttributeMaxDynamicSharedMemorySize, SMEM);
    cudaFuncSetAttribute(hgemm<1>, cudaFuncAttributeMaxDynamicSharedMemorySize, SMEM);
    cudaFuncSetAttribute(hgemm<2>, cudaFuncAttributeMaxDynamicSharedMemorySize, SMEM);

    {
        int n4;
        n4 = NTOK * HID / 4;   split_kernel<<<(n4 + 255) / 256, 256>>>(X, Xh, Xl, n4);
        n4 = INTER * HID / 4;  split_kernel<<<(n4 + 255) / 256, 256>>>(w_gate, Wgh, Wgl, n4);
        n4 = INTER * HID / 4;  split_kernel<<<(n4 + 255) / 256, 256>>>(w_up, Wuh, Wul, n4);
        n4 = HID * INTER / 4;  split_kernel<<<(n4 + 255) / 256, 256>>>(w_down, Wdh, Wdl, n4);
        n4 = 128 * HID / 4;    split_kernel<<<(n4 + 255) / 256, 256>>>(w_router, Wrh, Wrl, n4);
    }
    // router logits (layout == flat (2,n,64))
    hgemm<0><<<dim3(NTOK / 128, 1), 256, SMEM>>>(Xh, Xl, Wrh, Wrl, HID,
                                                 logits, 128, nullptr, nullptr, nullptr);
    routing_kernel<<<NTOK / 256, 256>>>(logits);
    experts_kernel<<<NTOK, 256>>>(X, down_e, up_e, out);
    // G = X@Wg^T
    hgemm<0><<<dim3(NTOK / 128, INTER / 128), 256, SMEM>>>(Xh, Xl, Wgh, Wgl, HID,
                                                           G, INTER, nullptr, nullptr, nullptr);
    // H = silu(G) * (X@Wu^T) -> split planes
    hgemm<1><<<dim3(NTOK / 128, INTER / 128), 256, SMEM>>>(Xh, Xl, Wuh, Wul, HID,
                                                           nullptr, INTER, G, Hh, Hl);
    // out += H @ Wd^T
    hgemm<2><<<dim3(NTOK / 128, HID / 128), 256, SMEM>>>(Hh, Hl, Wdh, Wdl, INTER,
                                                         out, HID, nullptr, nullptr, nullptr);
    (void)in_sizes; (void)n_in; (void)out_size;
}

// round 5
// speedup vs baseline: 4.0830x; 2.0960x over previous
#include <cuda_runtime.h>
#include <cuda_fp16.h>
#include <cstdint>
#include <math.h>

#define HID    1024
#define INTER  4096
#define NTOK   4096
#define NKEYS  64
#define TOPK   8

typedef unsigned short u16;
typedef unsigned int   u32;

// ---------------- scratch (no allocations allowed) ----------------
__device__ __align__(16) static u16   g_Xh[(size_t)NTOK * HID];
__device__ __align__(16) static u16   g_Xl[(size_t)NTOK * HID];
__device__ __align__(16) static u16   g_Wgh[(size_t)INTER * HID];
__device__ __align__(16) static u16   g_Wuh[(size_t)INTER * HID];
__device__ __align__(16) static u16   g_Wdh[(size_t)HID * INTER];
__device__ __align__(16) static u16   g_Wrh[(size_t)128 * HID];
__device__ __align__(16) static u16   g_Wrl[(size_t)128 * HID];
__device__ __align__(16) static u16   g_Hh[(size_t)NTOK * INTER];
__device__ __align__(16) static float g_G[(size_t)NTOK * INTER];
__device__ static int   g_tidx[NTOK * TOPK];
__device__ static float g_tw[NTOK * TOPK];

// ---------------- helpers ----------------
__device__ __forceinline__ u32 smem_u32(const void* p) {
    u32 a;
    asm("{ .reg .u64 t; cvta.to.shared.u64 t, %1; cvt.u32.u64 %0, t; }" : "=r"(a) : "l"(p));
    return a;
}

__device__ __forceinline__ void cp16(u32 dst, const void* src) {
    asm volatile("cp.async.cg.shared.global [%0], [%1], 16;" :: "r"(dst), "l"(src));
}
#define CP_COMMIT() asm volatile("cp.async.commit_group;" ::: "memory")
#define CP_WAIT(n)  asm volatile("cp.async.wait_group %0;" :: "n"(n) : "memory")

__device__ __forceinline__ void ldsm_x4(u32& r0, u32& r1, u32& r2, u32& r3, u32 addr) {
    asm volatile("ldmatrix.sync.aligned.m8n8.x4.shared.b16 {%0,%1,%2,%3}, [%4];"
                 : "=r"(r0), "=r"(r1), "=r"(r2), "=r"(r3) : "r"(addr));
}
__device__ __forceinline__ void ldsm_x2(u32& r0, u32& r1, u32 addr) {
    asm volatile("ldmatrix.sync.aligned.m8n8.x2.shared.b16 {%0,%1}, [%2];"
                 : "=r"(r0), "=r"(r1) : "r"(addr));
}

__device__ __forceinline__ void mma_f32(float* c, const u32* a, const u32* b) {
    asm volatile(
        "mma.sync.aligned.m16n8k16.row.col.f32.f16.f16.f32 "
        "{%0,%1,%2,%3}, {%4,%5,%6,%7}, {%8,%9}, {%0,%1,%2,%3};"
        : "+f"(c[0]), "+f"(c[1]), "+f"(c[2]), "+f"(c[3])
        : "r"(a[0]), "r"(a[1]), "r"(a[2]), "r"(a[3]), "r"(b[0]), "r"(b[1]));
}
__device__ __forceinline__ void mma_f16(u32* c, const u32* a, const u32* b) {
    asm volatile(
        "mma.sync.aligned.m16n8k16.row.col.f16.f16.f16.f16 "
        "{%0,%1}, {%2,%3,%4,%5}, {%6,%7}, {%0,%1};"
        : "+r"(c[0]), "+r"(c[1])
        : "r"(a[0]), "r"(a[1]), "r"(a[2]), "r"(a[3]), "r"(b[0]), "r"(b[1]));
}

__device__ __forceinline__ float silu(float x) { return x / (1.f + expf(-x)); }

// ---------------- fp32 -> fp16 splits ----------------
__global__ void split2_kernel(const float* __restrict__ src,
                              u16* __restrict__ hi, u16* __restrict__ lo, int n4)
{
    int i = blockIdx.x * blockDim.x + threadIdx.x;
    if (i >= n4) return;
    float4 v = ((const float4*)src)[i];
    __half hx = __float2half_rn(v.x), hy = __float2half_rn(v.y);
    __half hz = __float2half_rn(v.z), hw = __float2half_rn(v.w);
    __half lx = __float2half_rn(v.x - __half2float(hx));
    __half ly = __float2half_rn(v.y - __half2float(hy));
    __half lz = __float2half_rn(v.z - __half2float(hz));
    __half lw = __float2half_rn(v.w - __half2float(hw));
    __half2 h0 = __halves2half2(hx, hy), h1 = __halves2half2(hz, hw);
    __half2 l0 = __halves2half2(lx, ly), l1 = __halves2half2(lz, lw);
    ((uint2*)hi)[i] = make_uint2(*(u32*)&h0, *(u32*)&h1);
    ((uint2*)lo)[i] = make_uint2(*(u32*)&l0, *(u32*)&l1);
}

__global__ void split1_kernel(const float* __restrict__ src,
                              u16* __restrict__ hi, int n4)
{
    int i = blockIdx.x * blockDim.x + threadIdx.x;
    if (i >= n4) return;
    float4 v = ((const float4*)src)[i];
    __half2 h0 = __halves2half2(__float2half_rn(v.x), __float2half_rn(v.y));
    __half2 h1 = __halves2half2(__float2half_rn(v.z), __float2half_rn(v.w));
    ((uint2*)hi)[i] = make_uint2(*(u32*)&h0, *(u32*)&h1);
}

#define PITCH 80
#define PLANE 10240                   // 128 * 80

// =====================================================================
// hgemm1: single-product fp16 HMMA GEMM. C[M,N] = A[M,K] @ B[N,K]^T.
// CTA tile 128x128, BK=32, 8 warps (warp 64x32), 3-stage cp.async, occ 2.
// MODE 0: C = P ; MODE 1: H = silu(G)*P -> fp16 plane ; MODE 2: C += P
// =====================================================================
#define STG1 20480                    // 2 planes

template<int MODE>
__global__ __launch_bounds__(256, 2)
void hgemm1(const u16* __restrict__ A_h, const u16* __restrict__ B_h,
            int K, float* __restrict__ C, int ldC,
            const float* __restrict__ Gin, u16* __restrict__ Hh)
{
    extern __shared__ char sm[];
    const u32 sb = smem_u32(sm);
    const int tid  = threadIdx.x;
    const int lane = tid & 31;
    const int wid  = tid >> 5;
    const int row0 = blockIdx.x * 128;
    const int col0 = blockIdx.y * 128;
    const int warpM = (wid >> 2) * 64;
    const int warpN = (wid & 3) * 32;

    const int f  = tid * 2;
    const int lr = f >> 2;
    const int c0 = f & 3;

    const int NS = K >> 5;

    auto load_stage = [&](int kt, int buf) {
        const size_t goA = (size_t)(row0 + lr) * K + kt * 32;
        const size_t goB = (size_t)(col0 + lr) * K + kt * 32;
        const u32 so = sb + buf * STG1 + lr * PITCH;
        cp16(so + c0 * 16,                  A_h + goA + c0 * 8);
        cp16(so + (c0 + 1) * 16,            A_h + goA + (c0 + 1) * 8);
        cp16(so + PLANE + c0 * 16,          B_h + goB + c0 * 8);
        cp16(so + PLANE + (c0 + 1) * 16,    B_h + goB + (c0 + 1) * 8);
    };

    float acc[4][4][4];
    #pragma unroll
    for (int i = 0; i < 4; i++)
        #pragma unroll
        for (int j = 0; j < 4; j++)
            #pragma unroll
            for (int t = 0; t < 4; t++) acc[i][j][t] = 0.f;

    const int l4 = lane & 15;
    const u32 aRowOff = (u32)((lane & 15) * PITCH + ((lane >> 4) << 4));
    const u32 bRowOff = (u32)((l4 & 7) * PITCH + ((l4 >> 3) << 4));

    load_stage(0, 0); CP_COMMIT();
    load_stage(1, 1); CP_COMMIT();

    for (int s = 0; s < NS; s++) {
        const int buf = s % 3;
        CP_WAIT(1);
        __syncthreads();
        if (s + 2 < NS) load_stage(s + 2, (s + 2) % 3);
        CP_COMMIT();

        const u32 stg = sb + buf * STG1;
        #pragma unroll
        for (int ks = 0; ks < 2; ks++) {
            const u32 kb = ks * 32;
            u32 ah[4][4], bh[4][2];
            #pragma unroll
            for (int i = 0; i < 4; i++)
                ldsm_x4(ah[i][0], ah[i][1], ah[i][2], ah[i][3],
                        stg + (warpM + i * 16) * PITCH + kb + aRowOff);
            #pragma unroll
            for (int j = 0; j < 4; j++)
                ldsm_x2(bh[j][0], bh[j][1],
                        stg + PLANE + (warpN + j * 8) * PITCH + kb + bRowOff);
            #pragma unroll
            for (int i = 0; i < 4; i++)
                #pragma unroll
                for (int j = 0; j < 4; j++) mma_f32(acc[i][j], ah[i], bh[j]);
        }
    }

    #pragma unroll
    for (int i = 0; i < 4; i++) {
        #pragma unroll
        for (int j = 0; j < 4; j++) {
            const int r = row0 + warpM + i * 16 + (lane >> 2);
            const int c = col0 + warpN + j * 8 + (lane & 3) * 2;
            #pragma unroll
            for (int half = 0; half < 2; half++) {
                const int rr = r + half * 8;
                const float v0 = acc[i][j][half * 2 + 0];
                const float v1 = acc[i][j][half * 2 + 1];
                if (MODE == 0) {
                    *(float2*)(C + (size_t)rr * ldC + c) = make_float2(v0, v1);
                } else if (MODE == 1) {
                    float2 g = *(const float2*)(Gin + (size_t)rr * ldC + c);
                    __half2 hp = __halves2half2(__float2half_rn(silu(g.x) * v0),
                                                __float2half_rn(silu(g.y) * v1));
                    ((u32*)Hh)[((size_t)rr * ldC + c) >> 1] = *(u32*)&hp;
                } else {
                    float2 prev = *(const float2*)(C + (size_t)rr * ldC + c);
                    *(float2*)(C + (size_t)rr * ldC + c) =
                        make_float2(prev.x + v0, prev.y + v1);
                }
            }
        }
    }
}

// =====================================================================
// hgemm3: fp16x3 split GEMM (router only) — hi*hi f32 acc, cross f16 acc.
// =====================================================================
#define STG3 40960                    // 4 planes

__global__ __launch_bounds__(256, 1)
void hgemm3(const u16* __restrict__ A_h, const u16* __restrict__ A_l,
            const u16* __restrict__ B_h, const u16* __restrict__ B_l,
            int K, float* __restrict__ C, int ldC)
{
    extern __shared__ char sm[];
    const u32 sb = smem_u32(sm);
    const int tid  = threadIdx.x;
    const int lane = tid & 31;
    const int wid  = tid >> 5;
    const int row0 = blockIdx.x * 128;
    const int col0 = blockIdx.y * 128;
    const int warpM = (wid >> 2) * 64;
    const int warpN = (wid & 3) * 32;

    const int f  = tid * 2;
    const int lr = f >> 2;
    const int c0 = f & 3;

    const int NS = K >> 5;

    auto load_stage = [&](int kt, int buf) {
        const size_t goA = (size_t)(row0 + lr) * K + kt * 32;
        const size_t goB = (size_t)(col0 + lr) * K + kt * 32;
        const u32 so = sb + buf * STG3 + lr * PITCH;
        cp16(so + 0 * PLANE + c0 * 16,       A_h + goA + c0 * 8);
        cp16(so + 0 * PLANE + (c0 + 1) * 16, A_h + goA + (c0 + 1) * 8);
        cp16(so + 1 * PLANE + c0 * 16,       A_l + goA + c0 * 8);
        cp16(so + 1 * PLANE + (c0 + 1) * 16, A_l + goA + (c0 + 1) * 8);
        cp16(so + 2 * PLANE + c0 * 16,       B_h + goB + c0 * 8);
        cp16(so + 2 * PLANE + (c0 + 1) * 16, B_h + goB + (c0 + 1) * 8);
        cp16(so + 3 * PLANE + c0 * 16,       B_l + goB + c0 * 8);
        cp16(so + 3 * PLANE + (c0 + 1) * 16, B_l + goB + (c0 + 1) * 8);
    };

    float acc[4][4][4];
    u32   accX[4][4][2];
    #pragma unroll
    for (int i = 0; i < 4; i++)
        #pragma unroll
        for (int j = 0; j < 4; j++) {
            #pragma unroll
            for (int t = 0; t < 4; t++) acc[i][j][t] = 0.f;
            accX[i][j][0] = 0u; accX[i][j][1] = 0u;
        }

    const int l4 = lane & 15;
    const u32 aRowOff = (u32)((lane & 15) * PITCH + ((lane >> 4) << 4));
    const u32 bRowOff = (u32)((l4 & 7) * PITCH + ((l4 >> 3) << 4));

    load_stage(0, 0); CP_COMMIT();
    load_stage(1, 1); CP_COMMIT();

    for (int s = 0; s < NS; s++) {
        const int buf = s % 3;
        CP_WAIT(1);
        __syncthreads();
        if (s + 2 < NS) load_stage(s + 2, (s + 2) % 3);
        CP_COMMIT();

        const u32 stg = sb + buf * STG3;
        #pragma unroll
        for (int ks = 0; ks < 2; ks++) {
            const u32 kb = ks * 32;
            u32 ah[4][4], al[4][4], bh[4][2], bl[4][2];
            #pragma unroll
            for (int i = 0; i < 4; i++) {
                const u32 ra = stg + (warpM + i * 16) * PITCH + kb + aRowOff;
                ldsm_x4(ah[i][0], ah[i][1], ah[i][2], ah[i][3], ra);
                ldsm_x4(al[i][0], al[i][1], al[i][2], al[i][3], ra + PLANE);
            }
            #pragma unroll
            for (int j = 0; j < 4; j++) {
                const u32 rb = stg + 2 * PLANE + (warpN + j * 8) * PITCH + kb + bRowOff;
                ldsm_x2(bh[j][0], bh[j][1], rb);
                ldsm_x2(bl[j][0], bl[j][1], rb + PLANE);
            }
            #pragma unroll
            for (int i = 0; i < 4; i++)
                #pragma unroll
                for (int j = 0; j < 4; j++) mma_f32(acc[i][j], ah[i], bh[j]);
            #pragma unroll
            for (int i = 0; i < 4; i++)
                #pragma unroll
                for (int j = 0; j < 4; j++) {
                    mma_f16(accX[i][j], ah[i], bl[j]);
                    mma_f16(accX[i][j], al[i], bh[j]);
                }
        }
    }

    #pragma unroll
    for (int i = 0; i < 4; i++) {
        #pragma unroll
        for (int j = 0; j < 4; j++) {
            float2 x0 = __half22float2(*(__half2*)&accX[i][j][0]);
            float2 x1 = __half22float2(*(__half2*)&accX[i][j][1]);
            const float vv[4] = { acc[i][j][0] + x0.x, acc[i][j][1] + x0.y,
                                  acc[i][j][2] + x1.x, acc[i][j][3] + x1.y };
            const int r = row0 + warpM + i * 16 + (lane >> 2);
            const int c = col0 + warpN + j * 8 + (lane & 3) * 2;
            #pragma unroll
            for (int half = 0; half < 2; half++) {
                const int rr = r + half * 8;
                *(float2*)(C + (size_t)rr * ldC + c) =
                    make_float2(vv[half * 2 + 0], vv[half * 2 + 1]);
            }
        }
    }
}

// ---------------- routing ----------------
__device__ __forceinline__ void top8_insert(float v, int idx, float* hv, int* hi) {
    if (v <= hv[7]) return;
    int p = 7;
    #pragma unroll
    for (int q = 7; q > 0; q--) {
        if (v > hv[q-1]) { hv[q] = hv[q-1]; hi[q] = hi[q-1]; p = q - 1; }
    }
    hv[p] = v; hi[p] = idx;
}

__global__ void routing_kernel(const float* __restrict__ logits)
{
    int m = blockIdx.x * blockDim.x + threadIdx.x;
    if (m >= NTOK) return;

    const float* px = logits + (size_t)(m >> 1) * 128 + (m & 1) * 64;
    const float* py = logits + (size_t)(2048 + (m >> 1)) * 128 + (m & 1) * 64;

    float vx[8], vy[8];
    int   ix[8], iy[8];
    #pragma unroll
    for (int t = 0; t < 8; t++) { vx[t] = -3.4e38f; vy[t] = -3.4e38f; ix[t] = 0; iy[t] = 0; }
    for (int k = 0; k < NKEYS; k++) top8_insert(px[k], k, vx, ix);
    for (int k = 0; k < NKEYS; k++) top8_insert(py[k], k, vy, iy);

    float sv[8]; int sa[8];
    #pragma unroll
    for (int t = 0; t < 8; t++) { sv[t] = -3.4e38f; sa[t] = 0; }
    for (int a = 0; a < 8; a++)
        for (int b = 0; b < 8; b++)
            top8_insert(vx[a] + vy[b], a * 8 + b, sv, sa);

    float mx = sv[0];
    float e[8], s = 0.f;
    #pragma unroll
    for (int t = 0; t < 8; t++) { e[t] = expf(sv[t] - mx); s += e[t]; }
    float w[8], s2 = 0.f;
    #pragma unroll
    for (int t = 0; t < 8; t++) { w[t] = e[t] / s; s2 += w[t]; }
    #pragma unroll
    for (int t = 0; t < 8; t++) w[t] /= s2;

    #pragma unroll
    for (int t = 0; t < 8; t++) {
        int a = sa[t] >> 3, b = sa[t] & 7;
        g_tidx[m * TOPK + t] = ix[a] * NKEYS + iy[b];
        g_tw[m * TOPK + t]   = w[t];
    }
}

// ---------------- experts ----------------
__global__ __launch_bounds__(256)
void experts_kernel(const float* __restrict__ X,
                    const float* __restrict__ down_e,
                    const float* __restrict__ up_e,
                    float* __restrict__ out)
{
    __shared__ float4 xs4[HID / 4];
    __shared__ float  ews[TOPK];

    const int m   = blockIdx.x;
    const int tid = threadIdx.x;

    xs4[tid] = ((const float4*)(X + (size_t)m * HID))[tid];
    __syncthreads();

    const float* xs = (const float*)xs4;
    const int wid  = tid >> 5;
    const int lane = tid & 31;

    {
        int e = g_tidx[m * TOPK + wid];
        const float* d = down_e + (size_t)e * HID;
        float s = 0.f;
        for (int k = lane; k < HID; k += 32) s = fmaf(d[k], xs[k], s);
        #pragma unroll
        for (int o = 16; o; o >>= 1) s += __shfl_xor_sync(0xffffffffu, s, o);
        if (lane == 0) {
            float sig = s / (1.f + expf(-s));
            ews[wid] = sig * g_tw[m * TOPK + wid];
        }
    }
    __syncthreads();

    float4 acc = make_float4(0.f, 0.f, 0.f, 0.f);
    #pragma unroll
    for (int k = 0; k < TOPK; k++) {
        int e = g_tidx[m * TOPK + k];
        float w = ews[k];
        float4 u = ((const float4*)(up_e + (size_t)e * HID))[tid];
        acc.x = fmaf(w, u.x, acc.x);
        acc.y = fmaf(w, u.y, acc.y);
        acc.z = fmaf(w, u.z, acc.z);
        acc.w = fmaf(w, u.w, acc.w);
    }
    ((float4*)(out + (size_t)m * HID))[tid] = acc;
}

// ---------------- launch ----------------
static void* sym(const void* s) { void* p = nullptr; cudaGetSymbolAddress(&p, s); return p; }

extern "C" void kernel_launch(void* const* d_in, const int* in_sizes, int n_in,
                              void* d_out, int out_size)
{
    const float* X        = (const float*)d_in[0];
    const float* w_gate   = (const float*)d_in[1];
    const float* w_up     = (const float*)d_in[2];
    const float* w_down   = (const float*)d_in[3];
    const float* w_router = (const float*)d_in[4];
    const float* down_e   = (const float*)d_in[5];
    const float* up_e     = (const float*)d_in[6];

    float* out    = (float*)d_out;
    float* logits = (float*)d_out + (size_t)NTOK * HID;

    u16 *Xh = (u16*)sym(g_Xh),  *Xl = (u16*)sym(g_Xl);
    u16 *Wgh = (u16*)sym(g_Wgh);
    u16 *Wuh = (u16*)sym(g_Wuh);
    u16 *Wdh = (u16*)sym(g_Wdh);
    u16 *Wrh = (u16*)sym(g_Wrh), *Wrl = (u16*)sym(g_Wrl);
    u16 *Hh = (u16*)sym(g_Hh);
    float* G = (float*)sym(g_G);

    const int SMEM1 = 3 * STG1;   // 61440
    const int SMEM3 = 3 * STG3;   // 122880
    cudaFuncSetAttribute(hgemm1<0>, cudaFuncAttributeMaxDynamicSharedMemorySize, SMEM1);
    cudaFuncSetAttribute(hgemm1<1>, cudaFuncAttributeMaxDynamicSharedMemorySize, SMEM1);
    cudaFuncSetAttribute(hgemm1<2>, cudaFuncAttributeMaxDynamicSharedMemorySize, SMEM1);
    cudaFuncSetAttribute(hgemm3,    cudaFuncAttributeMaxDynamicSharedMemorySize, SMEM3);

    {
        int n4;
        n4 = NTOK * HID / 4;   split2_kernel<<<(n4 + 255) / 256, 256>>>(X, Xh, Xl, n4);
        n4 = 128 * HID / 4;    split2_kernel<<<(n4 + 255) / 256, 256>>>(w_router, Wrh, Wrl, n4);
        n4 = INTER * HID / 4;  split1_kernel<<<(n4 + 255) / 256, 256>>>(w_gate, Wgh, n4);
        n4 = INTER * HID / 4;  split1_kernel<<<(n4 + 255) / 256, 256>>>(w_up, Wuh, n4);
        n4 = HID * INTER / 4;  split1_kernel<<<(n4 + 255) / 256, 256>>>(w_down, Wdh, n4);
    }
    // router logits (fp16x3, near-exact -> stable expert selection)
    hgemm3<<<dim3(NTOK / 128, 1), 256, SMEM3>>>(Xh, Xl, Wrh, Wrl, HID, logits, 128);
    routing_kernel<<<NTOK / 256, 256>>>(logits);
    experts_kernel<<<NTOK, 256>>>(X, down_e, up_e, out);
    // G = X@Wg^T
    hgemm1<0><<<dim3(NTOK / 128, INTER / 128), 256, SMEM1>>>(Xh, Wgh, HID, G, INTER,
                                                             nullptr, nullptr);
    // H = silu(G) * (X@Wu^T) -> fp16 plane
    hgemm1<1><<<dim3(NTOK / 128, INTER / 128), 256, SMEM1>>>(Xh, Wuh, HID, nullptr, INTER,
                                                             G, Hh);
    // out += H @ Wd^T
    hgemm1<2><<<dim3(NTOK / 128, HID / 128), 256, SMEM1>>>(Hh, Wdh, INTER, out, HID,
                                                           nullptr, nullptr);
    (void)in_sizes; (void)n_in; (void)out_size;
}

// round 6
// speedup vs baseline: 4.5194x; 1.1069x over previous
#include <cuda_runtime.h>
#include <cuda_fp16.h>
#include <cstdint>
#include <math.h>

#define HID    1024
#define INTER  4096
#define NTOK   4096
#define NKEYS  64
#define TOPK   8

typedef unsigned short u16;
typedef unsigned int   u32;

// ---------------- scratch (no allocations allowed) ----------------
__device__ __align__(16) static u16   g_Xh[(size_t)NTOK * HID];
__device__ __align__(16) static u16   g_Xl[(size_t)NTOK * HID];
__device__ __align__(16) static u16   g_Wgh[(size_t)INTER * HID];
__device__ __align__(16) static u16   g_Wuh[(size_t)INTER * HID];
__device__ __align__(16) static u16   g_Wdh[(size_t)HID * INTER];
__device__ __align__(16) static u16   g_Wrh[(size_t)128 * HID];
__device__ __align__(16) static u16   g_Wrl[(size_t)128 * HID];
__device__ __align__(16) static u16   g_Hh[(size_t)NTOK * INTER];
__device__ static int   g_tidx[NTOK * TOPK];
__device__ static float g_tw[NTOK * TOPK];

// ---------------- helpers ----------------
__device__ __forceinline__ u32 smem_u32(const void* p) {
    u32 a;
    asm("{ .reg .u64 t; cvta.to.shared.u64 t, %1; cvt.u32.u64 %0, t; }" : "=r"(a) : "l"(p));
    return a;
}

__device__ __forceinline__ void cp16(u32 dst, const void* src) {
    asm volatile("cp.async.cg.shared.global [%0], [%1], 16;" :: "r"(dst), "l"(src));
}
#define CP_COMMIT() asm volatile("cp.async.commit_group;" ::: "memory")
#define CP_WAIT(n)  asm volatile("cp.async.wait_group %0;" :: "n"(n) : "memory")

__device__ __forceinline__ void ldsm_x4(u32& r0, u32& r1, u32& r2, u32& r3, u32 addr) {
    asm volatile("ldmatrix.sync.aligned.m8n8.x4.shared.b16 {%0,%1,%2,%3}, [%4];"
                 : "=r"(r0), "=r"(r1), "=r"(r2), "=r"(r3) : "r"(addr));
}
__device__ __forceinline__ void ldsm_x2(u32& r0, u32& r1, u32 addr) {
    asm volatile("ldmatrix.sync.aligned.m8n8.x2.shared.b16 {%0,%1}, [%2];"
                 : "=r"(r0), "=r"(r1) : "r"(addr));
}

__device__ __forceinline__ void mma_f32(float* c, const u32* a, const u32* b) {
    asm volatile(
        "mma.sync.aligned.m16n8k16.row.col.f32.f16.f16.f32 "
        "{%0,%1,%2,%3}, {%4,%5,%6,%7}, {%8,%9}, {%0,%1,%2,%3};"
        : "+f"(c[0]), "+f"(c[1]), "+f"(c[2]), "+f"(c[3])
        : "r"(a[0]), "r"(a[1]), "r"(a[2]), "r"(a[3]), "r"(b[0]), "r"(b[1]));
}
__device__ __forceinline__ void mma_f16(u32* c, const u32* a, const u32* b) {
    asm volatile(
        "mma.sync.aligned.m16n8k16.row.col.f16.f16.f16.f16 "
        "{%0,%1}, {%2,%3,%4,%5}, {%6,%7}, {%0,%1};"
        : "+r"(c[0]), "+r"(c[1])
        : "r"(a[0]), "r"(a[1]), "r"(a[2]), "r"(a[3]), "r"(b[0]), "r"(b[1]));
}

__device__ __forceinline__ float silu(float x) { return x / (1.f + expf(-x)); }

// ---------------- fp32 -> fp16 splits ----------------
__global__ void split2_kernel(const float* __restrict__ src,
                              u16* __restrict__ hi, u16* __restrict__ lo, int n4)
{
    int i = blockIdx.x * blockDim.x + threadIdx.x;
    if (i >= n4) return;
    float4 v = ((const float4*)src)[i];
    __half hx = __float2half_rn(v.x), hy = __float2half_rn(v.y);
    __half hz = __float2half_rn(v.z), hw = __float2half_rn(v.w);
    __half lx = __float2half_rn(v.x - __half2float(hx));
    __half ly = __float2half_rn(v.y - __half2float(hy));
    __half lz = __float2half_rn(v.z - __half2float(hz));
    __half lw = __float2half_rn(v.w - __half2float(hw));
    __half2 h0 = __halves2half2(hx, hy), h1 = __halves2half2(hz, hw);
    __half2 l0 = __halves2half2(lx, ly), l1 = __halves2half2(lz, lw);
    ((uint2*)hi)[i] = make_uint2(*(u32*)&h0, *(u32*)&h1);
    ((uint2*)lo)[i] = make_uint2(*(u32*)&l0, *(u32*)&l1);
}

// three equal-size fp32->fp16 plane conversions in one launch (blockIdx.y picks)
__global__ void split1x3_kernel(const float* __restrict__ s0, u16* __restrict__ d0,
                                const float* __restrict__ s1, u16* __restrict__ d1,
                                const float* __restrict__ s2, u16* __restrict__ d2,
                                int n4)
{
    int i = blockIdx.x * blockDim.x + threadIdx.x;
    if (i >= n4) return;
    const float* src = (blockIdx.y == 0) ? s0 : (blockIdx.y == 1) ? s1 : s2;
    u16* dst = (blockIdx.y == 0) ? d0 : (blockIdx.y == 1) ? d1 : d2;
    float4 v = ((const float4*)src)[i];
    __half2 h0 = __halves2half2(__float2half_rn(v.x), __float2half_rn(v.y));
    __half2 h1 = __halves2half2(__float2half_rn(v.z), __float2half_rn(v.w));
    ((uint2*)dst)[i] = make_uint2(*(u32*)&h0, *(u32*)&h1);
}

#define PITCH 80
#define PLANE 10240                   // 128 * 80
#define STG4  40960                   // 4-plane stage stride (shared by both paths)

// =====================================================================
// mlp1_kernel: one launch, grid (32, 33).
//  blockIdx.y < 32 : fused gate/up — Hh = f16(silu(X@Wg^T) * (X@Wu^T))
//  blockIdx.y == 32: router — logits = X@Wr^T via fp16x3 (near-exact)
// CTA tile 128x128, BK=32, 8 warps (warp 64x32), 3-stage cp.async.
// =====================================================================
__global__ __launch_bounds__(256, 1)
void mlp1_kernel(const u16* __restrict__ Xh, const u16* __restrict__ Xl,
                 const u16* __restrict__ Wgh, const u16* __restrict__ Wuh,
                 const u16* __restrict__ Wrh, const u16* __restrict__ Wrl,
                 u16* __restrict__ Hh, float* __restrict__ logits)
{
    extern __shared__ char sm[];
    const u32 sb = smem_u32(sm);
    const int tid  = threadIdx.x;
    const int lane = tid & 31;
    const int wid  = tid >> 5;
    const int row0 = blockIdx.x * 128;
    const int warpM = (wid >> 2) * 64;
    const int warpN = (wid & 3) * 32;

    const int f  = tid * 2;
    const int lr = f >> 2;
    const int c0 = f & 3;

    const int l4 = lane & 15;
    const u32 aRowOff = (u32)((lane & 15) * PITCH + ((lane >> 4) << 4));
    const u32 bRowOff = (u32)((l4 & 7) * PITCH + ((l4 >> 3) << 4));

    const int NS = HID >> 5;   // 32 stages

    if (blockIdx.y < gridDim.y - 1) {
        // ---------------- fused gate/up path ----------------
        const int col0 = blockIdx.y * 128;

        auto load_stage = [&](int kt, int buf) {
            const size_t goA = (size_t)(row0 + lr) * HID + kt * 32;
            const size_t goB = (size_t)(col0 + lr) * HID + kt * 32;
            const u32 so = sb + buf * STG4 + lr * PITCH;
            cp16(so + c0 * 16,                    Xh  + goA + c0 * 8);
            cp16(so + (c0 + 1) * 16,              Xh  + goA + (c0 + 1) * 8);
            cp16(so + PLANE + c0 * 16,            Wgh + goB + c0 * 8);
            cp16(so + PLANE + (c0 + 1) * 16,      Wgh + goB + (c0 + 1) * 8);
            cp16(so + 2 * PLANE + c0 * 16,        Wuh + goB + c0 * 8);
            cp16(so + 2 * PLANE + (c0 + 1) * 16,  Wuh + goB + (c0 + 1) * 8);
        };

        float accG[4][4][4], accU[4][4][4];
        #pragma unroll
        for (int i = 0; i < 4; i++)
            #pragma unroll
            for (int j = 0; j < 4; j++)
                #pragma unroll
                for (int t = 0; t < 4; t++) { accG[i][j][t] = 0.f; accU[i][j][t] = 0.f; }

        load_stage(0, 0); CP_COMMIT();
        load_stage(1, 1); CP_COMMIT();

        for (int s = 0; s < NS; s++) {
            const int buf = s % 3;
            CP_WAIT(1);
            __syncthreads();
            if (s + 2 < NS) load_stage(s + 2, (s + 2) % 3);
            CP_COMMIT();

            const u32 stg = sb + buf * STG4;
            #pragma unroll
            for (int ks = 0; ks < 2; ks++) {
                const u32 kb = ks * 32;
                u32 ah[4][4], bg[4][2], bu[4][2];
                #pragma unroll
                for (int i = 0; i < 4; i++)
                    ldsm_x4(ah[i][0], ah[i][1], ah[i][2], ah[i][3],
                            stg + (warpM + i * 16) * PITCH + kb + aRowOff);
                #pragma unroll
                for (int j = 0; j < 4; j++) {
                    const u32 rb = stg + PLANE + (warpN + j * 8) * PITCH + kb + bRowOff;
                    ldsm_x2(bg[j][0], bg[j][1], rb);
                    ldsm_x2(bu[j][0], bu[j][1], rb + PLANE);
                }
                #pragma unroll
                for (int i = 0; i < 4; i++)
                    #pragma unroll
                    for (int j = 0; j < 4; j++) {
                        mma_f32(accG[i][j], ah[i], bg[j]);
                        mma_f32(accU[i][j], ah[i], bu[j]);
                    }
            }
        }

        #pragma unroll
        for (int i = 0; i < 4; i++) {
            #pragma unroll
            for (int j = 0; j < 4; j++) {
                const int r = row0 + warpM + i * 16 + (lane >> 2);
                const int c = col0 + warpN + j * 8 + (lane & 3) * 2;
                #pragma unroll
                for (int half = 0; half < 2; half++) {
                    const int rr = r + half * 8;
                    const float gg0 = accG[i][j][half * 2 + 0];
                    const float gg1 = accG[i][j][half * 2 + 1];
                    const float uu0 = accU[i][j][half * 2 + 0];
                    const float uu1 = accU[i][j][half * 2 + 1];
                    __half2 hp = __halves2half2(__float2half_rn(silu(gg0) * uu0),
                                                __float2half_rn(silu(gg1) * uu1));
                    ((u32*)Hh)[((size_t)rr * INTER + c) >> 1] = *(u32*)&hp;
                }
            }
        }
    } else {
        // ---------------- router path (fp16x3, near-exact) ----------------
        auto load_stage = [&](int kt, int buf) {
            const size_t goA = (size_t)(row0 + lr) * HID + kt * 32;
            const size_t goB = (size_t)lr * HID + kt * 32;   // 128 router rows
            const u32 so = sb + buf * STG4 + lr * PITCH;
            cp16(so + 0 * PLANE + c0 * 16,       Xh  + goA + c0 * 8);
            cp16(so + 0 * PLANE + (c0 + 1) * 16, Xh  + goA + (c0 + 1) * 8);
            cp16(so + 1 * PLANE + c0 * 16,       Xl  + goA + c0 * 8);
            cp16(so + 1 * PLANE + (c0 + 1) * 16, Xl  + goA + (c0 + 1) * 8);
            cp16(so + 2 * PLANE + c0 * 16,       Wrh + goB + c0 * 8);
            cp16(so + 2 * PLANE + (c0 + 1) * 16, Wrh + goB + (c0 + 1) * 8);
            cp16(so + 3 * PLANE + c0 * 16,       Wrl + goB + c0 * 8);
            cp16(so + 3 * PLANE + (c0 + 1) * 16, Wrl + goB + (c0 + 1) * 8);
        };

        float acc[4][4][4];
        u32   accX[4][4][2];
        #pragma unroll
        for (int i = 0; i < 4; i++)
            #pragma unroll
            for (int j = 0; j < 4; j++) {
                #pragma unroll
                for (int t = 0; t < 4; t++) acc[i][j][t] = 0.f;
                accX[i][j][0] = 0u; accX[i][j][1] = 0u;
            }

        load_stage(0, 0); CP_COMMIT();
        load_stage(1, 1); CP_COMMIT();

        for (int s = 0; s < NS; s++) {
            const int buf = s % 3;
            CP_WAIT(1);
            __syncthreads();
            if (s + 2 < NS) load_stage(s + 2, (s + 2) % 3);
            CP_COMMIT();

            const u32 stg = sb + buf * STG4;
            #pragma unroll
            for (int ks = 0; ks < 2; ks++) {
                const u32 kb = ks * 32;
                u32 ah[4][4], al[4][4], bh[4][2], bl[4][2];
                #pragma unroll
                for (int i = 0; i < 4; i++) {
                    const u32 ra = stg + (warpM + i * 16) * PITCH + kb + aRowOff;
                    ldsm_x4(ah[i][0], ah[i][1], ah[i][2], ah[i][3], ra);
                    ldsm_x4(al[i][0], al[i][1], al[i][2], al[i][3], ra + PLANE);
                }
                #pragma unroll
                for (int j = 0; j < 4; j++) {
                    const u32 rb = stg + 2 * PLANE + (warpN + j * 8) * PITCH + kb + bRowOff;
                    ldsm_x2(bh[j][0], bh[j][1], rb);
                    ldsm_x2(bl[j][0], bl[j][1], rb + PLANE);
                }
                #pragma unroll
                for (int i = 0; i < 4; i++)
                    #pragma unroll
                    for (int j = 0; j < 4; j++) mma_f32(acc[i][j], ah[i], bh[j]);
                #pragma unroll
                for (int i = 0; i < 4; i++)
                    #pragma unroll
                    for (int j = 0; j < 4; j++) {
                        mma_f16(accX[i][j], ah[i], bl[j]);
                        mma_f16(accX[i][j], al[i], bh[j]);
                    }
            }
        }

        #pragma unroll
        for (int i = 0; i < 4; i++) {
            #pragma unroll
            for (int j = 0; j < 4; j++) {
                float2 x0 = __half22float2(*(__half2*)&accX[i][j][0]);
                float2 x1 = __half22float2(*(__half2*)&accX[i][j][1]);
                const float vv[4] = { acc[i][j][0] + x0.x, acc[i][j][1] + x0.y,
                                      acc[i][j][2] + x1.x, acc[i][j][3] + x1.y };
                const int r = row0 + warpM + i * 16 + (lane >> 2);
                const int c = warpN + j * 8 + (lane & 3) * 2;
                #pragma unroll
                for (int half = 0; half < 2; half++) {
                    const int rr = r + half * 8;
                    *(float2*)(logits + (size_t)rr * 128 + c) =
                        make_float2(vv[half * 2 + 0], vv[half * 2 + 1]);
                }
            }
        }
    }
}

// =====================================================================
// down GEMM: out += H @ Wd^T (single-product fp16, occ 2)
// =====================================================================
#define STG1 20480                    // 2 planes

__global__ __launch_bounds__(256, 2)
void down_kernel(const u16* __restrict__ A_h, const u16* __restrict__ B_h,
                 int K, float* __restrict__ C, int ldC)
{
    extern __shared__ char sm[];
    const u32 sb = smem_u32(sm);
    const int tid  = threadIdx.x;
    const int lane = tid & 31;
    const int wid  = tid >> 5;
    const int row0 = blockIdx.x * 128;
    const int col0 = blockIdx.y * 128;
    const int warpM = (wid >> 2) * 64;
    const int warpN = (wid & 3) * 32;

    const int f  = tid * 2;
    const int lr = f >> 2;
    const int c0 = f & 3;

    const int NS = K >> 5;

    auto load_stage = [&](int kt, int buf) {
        const size_t goA = (size_t)(row0 + lr) * K + kt * 32;
        const size_t goB = (size_t)(col0 + lr) * K + kt * 32;
        const u32 so = sb + buf * STG1 + lr * PITCH;
        cp16(so + c0 * 16,               A_h + goA + c0 * 8);
        cp16(so + (c0 + 1) * 16,         A_h + goA + (c0 + 1) * 8);
        cp16(so + PLANE + c0 * 16,       B_h + goB + c0 * 8);
        cp16(so + PLANE + (c0 + 1) * 16, B_h + goB + (c0 + 1) * 8);
    };

    float acc[4][4][4];
    #pragma unroll
    for (int i = 0; i < 4; i++)
        #pragma unroll
        for (int j = 0; j < 4; j++)
            #pragma unroll
            for (int t = 0; t < 4; t++) acc[i][j][t] = 0.f;

    const int l4 = lane & 15;
    const u32 aRowOff = (u32)((lane & 15) * PITCH + ((lane >> 4) << 4));
    const u32 bRowOff = (u32)((l4 & 7) * PITCH + ((l4 >> 3) << 4));

    load_stage(0, 0); CP_COMMIT();
    load_stage(1, 1); CP_COMMIT();

    for (int s = 0; s < NS; s++) {
        const int buf = s % 3;
        CP_WAIT(1);
        __syncthreads();
        if (s + 2 < NS) load_stage(s + 2, (s + 2) % 3);
        CP_COMMIT();

        const u32 stg = sb + buf * STG1;
        #pragma unroll
        for (int ks = 0; ks < 2; ks++) {
            const u32 kb = ks * 32;
            u32 ah[4][4], bh[4][2];
            #pragma unroll
            for (int i = 0; i < 4; i++)
                ldsm_x4(ah[i][0], ah[i][1], ah[i][2], ah[i][3],
                        stg + (warpM + i * 16) * PITCH + kb + aRowOff);
            #pragma unroll
            for (int j = 0; j < 4; j++)
                ldsm_x2(bh[j][0], bh[j][1],
                        stg + PLANE + (warpN + j * 8) * PITCH + kb + bRowOff);
            #pragma unroll
            for (int i = 0; i < 4; i++)
                #pragma unroll
                for (int j = 0; j < 4; j++) mma_f32(acc[i][j], ah[i], bh[j]);
        }
    }

    #pragma unroll
    for (int i = 0; i < 4; i++) {
        #pragma unroll
        for (int j = 0; j < 4; j++) {
            const int r = row0 + warpM + i * 16 + (lane >> 2);
            const int c = col0 + warpN + j * 8 + (lane & 3) * 2;
            #pragma unroll
            for (int half = 0; half < 2; half++) {
                const int rr = r + half * 8;
                float2 prev = *(const float2*)(C + (size_t)rr * ldC + c);
                *(float2*)(C + (size_t)rr * ldC + c) =
                    make_float2(prev.x + acc[i][j][half * 2 + 0],
                                prev.y + acc[i][j][half * 2 + 1]);
            }
        }
    }
}

// ---------------- routing ----------------
__device__ __forceinline__ void top8_insert(float v, int idx, float* hv, int* hi) {
    if (v <= hv[7]) return;
    int p = 7;
    #pragma unroll
    for (int q = 7; q > 0; q--) {
        if (v > hv[q-1]) { hv[q] = hv[q-1]; hi[q] = hi[q-1]; p = q - 1; }
    }
    hv[p] = v; hi[p] = idx;
}

__global__ void routing_kernel(const float* __restrict__ logits)
{
    int m = blockIdx.x * blockDim.x + threadIdx.x;
    if (m >= NTOK) return;

    const float* px = logits + (size_t)(m >> 1) * 128 + (m & 1) * 64;
    const float* py = logits + (size_t)(2048 + (m >> 1)) * 128 + (m & 1) * 64;

    float vx[8], vy[8];
    int   ix[8], iy[8];
    #pragma unroll
    for (int t = 0; t < 8; t++) { vx[t] = -3.4e38f; vy[t] = -3.4e38f; ix[t] = 0; iy[t] = 0; }
    for (int k = 0; k < NKEYS; k++) top8_insert(px[k], k, vx, ix);
    for (int k = 0; k < NKEYS; k++) top8_insert(py[k], k, vy, iy);

    float sv[8]; int sa[8];
    #pragma unroll
    for (int t = 0; t < 8; t++) { sv[t] = -3.4e38f; sa[t] = 0; }
    for (int a = 0; a < 8; a++)
        for (int b = 0; b < 8; b++)
            top8_insert(vx[a] + vy[b], a * 8 + b, sv, sa);

    float mx = sv[0];
    float e[8], s = 0.f;
    #pragma unroll
    for (int t = 0; t < 8; t++) { e[t] = expf(sv[t] - mx); s += e[t]; }
    float w[8], s2 = 0.f;
    #pragma unroll
    for (int t = 0; t < 8; t++) { w[t] = e[t] / s; s2 += w[t]; }
    #pragma unroll
    for (int t = 0; t < 8; t++) w[t] /= s2;

    #pragma unroll
    for (int t = 0; t < 8; t++) {
        int a = sa[t] >> 3, b = sa[t] & 7;
        g_tidx[m * TOPK + t] = ix[a] * NKEYS + iy[b];
        g_tw[m * TOPK + t]   = w[t];
    }
}

// ---------------- experts ----------------
__global__ __launch_bounds__(256)
void experts_kernel(const float* __restrict__ X,
                    const float* __restrict__ down_e,
                    const float* __restrict__ up_e,
                    float* __restrict__ out)
{
    __shared__ float4 xs4[HID / 4];
    __shared__ float  ews[TOPK];

    const int m   = blockIdx.x;
    const int tid = threadIdx.x;

    xs4[tid] = ((const float4*)(X + (size_t)m * HID))[tid];
    __syncthreads();

    const float* xs = (const float*)xs4;
    const int wid  = tid >> 5;
    const int lane = tid & 31;

    {
        int e = g_tidx[m * TOPK + wid];
        const float* d = down_e + (size_t)e * HID;
        float s = 0.f;
        for (int k = lane; k < HID; k += 32) s = fmaf(d[k], xs[k], s);
        #pragma unroll
        for (int o = 16; o; o >>= 1) s += __shfl_xor_sync(0xffffffffu, s, o);
        if (lane == 0) {
            float sig = s / (1.f + expf(-s));
            ews[wid] = sig * g_tw[m * TOPK + wid];
        }
    }
    __syncthreads();

    float4 acc = make_float4(0.f, 0.f, 0.f, 0.f);
    #pragma unroll
    for (int k = 0; k < TOPK; k++) {
        int e = g_tidx[m * TOPK + k];
        float w = ews[k];
        float4 u = ((const float4*)(up_e + (size_t)e * HID))[tid];
        acc.x = fmaf(w, u.x, acc.x);
        acc.y = fmaf(w, u.y, acc.y);
        acc.z = fmaf(w, u.z, acc.z);
        acc.w = fmaf(w, u.w, acc.w);
    }
    ((float4*)(out + (size_t)m * HID))[tid] = acc;
}

// ---------------- launch ----------------
static void* sym(const void* s) { void* p = nullptr; cudaGetSymbolAddress(&p, s); return p; }

extern "C" void kernel_launch(void* const* d_in, const int* in_sizes, int n_in,
                              void* d_out, int out_size)
{
    const float* X        = (const float*)d_in[0];
    const float* w_gate   = (const float*)d_in[1];
    const float* w_up     = (const float*)d_in[2];
    const float* w_down   = (const float*)d_in[3];
    const float* w_router = (const float*)d_in[4];
    const float* down_e   = (const float*)d_in[5];
    const float* up_e     = (const float*)d_in[6];

    float* out    = (float*)d_out;
    float* logits = (float*)d_out + (size_t)NTOK * HID;

    u16 *Xh = (u16*)sym(g_Xh),  *Xl = (u16*)sym(g_Xl);
    u16 *Wgh = (u16*)sym(g_Wgh);
    u16 *Wuh = (u16*)sym(g_Wuh);
    u16 *Wdh = (u16*)sym(g_Wdh);
    u16 *Wrh = (u16*)sym(g_Wrh), *Wrl = (u16*)sym(g_Wrl);
    u16 *Hh = (u16*)sym(g_Hh);

    const int SMEM_MLP1 = 3 * STG4;   // 122880
    const int SMEM_DOWN = 3 * STG1;   // 61440
    cudaFuncSetAttribute(mlp1_kernel, cudaFuncAttributeMaxDynamicSharedMemorySize, SMEM_MLP1);
    cudaFuncSetAttribute(down_kernel, cudaFuncAttributeMaxDynamicSharedMemorySize, SMEM_DOWN);

    // 0) splits
    {
        int n4 = NTOK * HID / 4;
        split2_kernel<<<(n4 + 255) / 256, 256>>>(X, Xh, Xl, n4);
        int r4 = 128 * HID / 4;
        split2_kernel<<<(r4 + 255) / 256, 256>>>(w_router, Wrh, Wrl, r4);
        int w4 = INTER * HID / 4;
        split1x3_kernel<<<dim3((w4 + 255) / 256, 3), 256>>>(w_gate, Wgh, w_up, Wuh,
                                                            w_down, Wdh, w4);
    }
    // 1) fused gate/up + router (one launch)
    mlp1_kernel<<<dim3(NTOK / 128, INTER / 128 + 1), 256, SMEM_MLP1>>>(
        Xh, Xl, Wgh, Wuh, Wrh, Wrl, Hh, logits);
    // 2) routing top-k
    routing_kernel<<<NTOK / 256, 256>>>(logits);
    // 3) expert states -> out (initializes it)
    experts_kernel<<<NTOK, 256>>>(X, down_e, up_e, out);
    // 4) out += H @ Wd^T
    down_kernel<<<dim3(NTOK / 128, HID / 128), 256, SMEM_DOWN>>>(Hh, Wdh, INTER, out, HID);
    (void)in_sizes; (void)n_in; (void)out_size;
}

// round 7
// speedup vs baseline: 4.9058x; 1.0855x over previous
#include <cuda_runtime.h>
#include <cuda_fp16.h>
#include <cstdint>
#include <math.h>

#define HID    1024
#define INTER  4096
#define NTOK   4096
#define NKEYS  64
#define TOPK   8

typedef unsigned short u16;
typedef unsigned int   u32;

// ---------------- scratch (no allocations allowed) ----------------
__device__ __align__(16) static u16   g_Xh[(size_t)NTOK * HID];
__device__ __align__(16) static u16   g_Xl[(size_t)NTOK * HID];
__device__ __align__(16) static u16   g_Wgh[(size_t)INTER * HID];
__device__ __align__(16) static u16   g_Wuh[(size_t)INTER * HID];
__device__ __align__(16) static u16   g_Wdh[(size_t)HID * INTER];
__device__ __align__(16) static u16   g_Wrh[(size_t)128 * HID];
__device__ __align__(16) static u16   g_Wrl[(size_t)128 * HID];
__device__ __align__(16) static u16   g_Hh[(size_t)NTOK * INTER];
__device__ static int   g_tidx[NTOK * TOPK];
__device__ static float g_tw[NTOK * TOPK];

// ---------------- helpers ----------------
__device__ __forceinline__ u32 smem_u32(const void* p) {
    u32 a;
    asm("{ .reg .u64 t; cvta.to.shared.u64 t, %1; cvt.u32.u64 %0, t; }" : "=r"(a) : "l"(p));
    return a;
}

__device__ __forceinline__ void cp16(u32 dst, const void* src) {
    asm volatile("cp.async.cg.shared.global [%0], [%1], 16;" :: "r"(dst), "l"(src));
}
#define CP_COMMIT() asm volatile("cp.async.commit_group;" ::: "memory")
#define CP_WAIT(n)  asm volatile("cp.async.wait_group %0;" :: "n"(n) : "memory")

__device__ __forceinline__ void ldsm_x4(u32& r0, u32& r1, u32& r2, u32& r3, u32 addr) {
    asm volatile("ldmatrix.sync.aligned.m8n8.x4.shared.b16 {%0,%1,%2,%3}, [%4];"
                 : "=r"(r0), "=r"(r1), "=r"(r2), "=r"(r3) : "r"(addr));
}
__device__ __forceinline__ void ldsm_x2(u32& r0, u32& r1, u32 addr) {
    asm volatile("ldmatrix.sync.aligned.m8n8.x2.shared.b16 {%0,%1}, [%2];"
                 : "=r"(r0), "=r"(r1) : "r"(addr));
}

__device__ __forceinline__ void mma_f32(float* c, const u32* a, const u32* b) {
    asm volatile(
        "mma.sync.aligned.m16n8k16.row.col.f32.f16.f16.f32 "
        "{%0,%1,%2,%3}, {%4,%5,%6,%7}, {%8,%9}, {%0,%1,%2,%3};"
        : "+f"(c[0]), "+f"(c[1]), "+f"(c[2]), "+f"(c[3])
        : "r"(a[0]), "r"(a[1]), "r"(a[2]), "r"(a[3]), "r"(b[0]), "r"(b[1]));
}
__device__ __forceinline__ void mma_f16(u32* c, const u32* a, const u32* b) {
    asm volatile(
        "mma.sync.aligned.m16n8k16.row.col.f16.f16.f16.f16 "
        "{%0,%1}, {%2,%3,%4,%5}, {%6,%7}, {%0,%1};"
        : "+r"(c[0]), "+r"(c[1])
        : "r"(a[0]), "r"(a[1]), "r"(a[2]), "r"(a[3]), "r"(b[0]), "r"(b[1]));
}

__device__ __forceinline__ float silu(float x) { return x / (1.f + expf(-x)); }

// ---------------- fp32 -> fp16 splits ----------------
__global__ void split2_kernel(const float* __restrict__ src,
                              u16* __restrict__ hi, u16* __restrict__ lo, int n4)
{
    int i = blockIdx.x * blockDim.x + threadIdx.x;
    if (i >= n4) return;
    float4 v = ((const float4*)src)[i];
    __half hx = __float2half_rn(v.x), hy = __float2half_rn(v.y);
    __half hz = __float2half_rn(v.z), hw = __float2half_rn(v.w);
    __half lx = __float2half_rn(v.x - __half2float(hx));
    __half ly = __float2half_rn(v.y - __half2float(hy));
    __half lz = __float2half_rn(v.z - __half2float(hz));
    __half lw = __float2half_rn(v.w - __half2float(hw));
    __half2 h0 = __halves2half2(hx, hy), h1 = __halves2half2(hz, hw);
    __half2 l0 = __halves2half2(lx, ly), l1 = __halves2half2(lz, lw);
    ((uint2*)hi)[i] = make_uint2(*(u32*)&h0, *(u32*)&h1);
    ((uint2*)lo)[i] = make_uint2(*(u32*)&l0, *(u32*)&l1);
}

__global__ void split1x3_kernel(const float* __restrict__ s0, u16* __restrict__ d0,
                                const float* __restrict__ s1, u16* __restrict__ d1,
                                const float* __restrict__ s2, u16* __restrict__ d2,
                                int n4)
{
    int i = blockIdx.x * blockDim.x + threadIdx.x;
    if (i >= n4) return;
    const float* src = (blockIdx.y == 0) ? s0 : (blockIdx.y == 1) ? s1 : s2;
    u16* dst = (blockIdx.y == 0) ? d0 : (blockIdx.y == 1) ? d1 : d2;
    float4 v = ((const float4*)src)[i];
    __half2 h0 = __halves2half2(__float2half_rn(v.x), __float2half_rn(v.y));
    __half2 h1 = __halves2half2(__float2half_rn(v.z), __float2half_rn(v.w));
    ((uint2*)dst)[i] = make_uint2(*(u32*)&h0, *(u32*)&h1);
}

#define PITCH 80
#define PLANE128 10240                // 128 rows * 80
#define PLANE64  5120                 // 64 rows * 80

// =====================================================================
// mlp1_kernel: grid (32, 66), 256 thr, occ 2. CTA tile 128(M)x64(N).
//  y < 64 : fused gate/up — Hh = f16(silu(X@Wg^T) * (X@Wu^T))
//  y >= 64: router (fp16x3) — logits columns [(y-64)*64 .. +64)
// 8 warps as 4(M)x2(N), warp tile 32x32. BK=32.
// smem: gate/up 3 stages x 20480; router 2 stages x 30720. (both 61440)
// =====================================================================
#define STG_GU 20480
#define STG_R  30720
#define SMEM_MLP1 61440

__global__ __launch_bounds__(256, 2)
void mlp1_kernel(const u16* __restrict__ Xh, const u16* __restrict__ Xl,
                 const u16* __restrict__ Wgh, const u16* __restrict__ Wuh,
                 const u16* __restrict__ Wrh, const u16* __restrict__ Wrl,
                 u16* __restrict__ Hh, float* __restrict__ logits)
{
    extern __shared__ char sm[];
    const u32 sb = smem_u32(sm);
    const int tid  = threadIdx.x;
    const int lane = tid & 31;
    const int wid  = tid >> 5;
    const int row0 = blockIdx.x * 128;
    const int warpM = (wid & 3) * 32;
    const int warpN = (wid >> 2) * 32;

    // A-plane cp.async mapping (128x32 halfs): 2 chunks/thread
    const int lrA = tid >> 1;
    const int cA  = (tid & 1) * 2;
    // B-plane mapping (64x32 halfs): 1 chunk/thread
    const int lrB = tid >> 2;
    const int cB  = tid & 3;

    const int l4 = lane & 15;
    const u32 aRowOff = (u32)((lane & 15) * PITCH + ((lane >> 4) << 4));
    const u32 bRowOff = (u32)((l4 & 7) * PITCH + ((l4 >> 3) << 4));

    const int NS = HID >> 5;   // 32 stages

    if (blockIdx.y < 64) {
        // ======== fused gate/up, 3-stage ========
        const int col0 = blockIdx.y * 64;

        auto load_stage = [&](int kt, int buf) {
            const u32 so = sb + buf * STG_GU;
            const size_t goA = (size_t)(row0 + lrA) * HID + kt * 32;
            cp16(so + lrA * PITCH + cA * 16,       Xh + goA + cA * 8);
            cp16(so + lrA * PITCH + (cA + 1) * 16, Xh + goA + (cA + 1) * 8);
            const size_t goB = (size_t)(col0 + lrB) * HID + kt * 32;
            cp16(so + PLANE128 + lrB * PITCH + cB * 16,            Wgh + goB + cB * 8);
            cp16(so + PLANE128 + PLANE64 + lrB * PITCH + cB * 16,  Wuh + goB + cB * 8);
        };

        float accG[2][4][4], accU[2][4][4];
        #pragma unroll
        for (int i = 0; i < 2; i++)
            #pragma unroll
            for (int j = 0; j < 4; j++)
                #pragma unroll
                for (int t = 0; t < 4; t++) { accG[i][j][t] = 0.f; accU[i][j][t] = 0.f; }

        load_stage(0, 0); CP_COMMIT();
        load_stage(1, 1); CP_COMMIT();

        for (int s = 0; s < NS; s++) {
            const int buf = s % 3;
            CP_WAIT(1);
            __syncthreads();
            if (s + 2 < NS) load_stage(s + 2, (s + 2) % 3);
            CP_COMMIT();

            const u32 stg = sb + buf * STG_GU;
            #pragma unroll
            for (int ks = 0; ks < 2; ks++) {
                const u32 kb = ks * 32;
                u32 ah[2][4], bg[4][2], bu[4][2];
                #pragma unroll
                for (int i = 0; i < 2; i++)
                    ldsm_x4(ah[i][0], ah[i][1], ah[i][2], ah[i][3],
                            stg + (warpM + i * 16) * PITCH + kb + aRowOff);
                #pragma unroll
                for (int j = 0; j < 4; j++) {
                    const u32 rb = stg + PLANE128 + (warpN + j * 8) * PITCH + kb + bRowOff;
                    ldsm_x2(bg[j][0], bg[j][1], rb);
                    ldsm_x2(bu[j][0], bu[j][1], rb + PLANE64);
                }
                #pragma unroll
                for (int i = 0; i < 2; i++)
                    #pragma unroll
                    for (int j = 0; j < 4; j++) {
                        mma_f32(accG[i][j], ah[i], bg[j]);
                        mma_f32(accU[i][j], ah[i], bu[j]);
                    }
            }
        }

        #pragma unroll
        for (int i = 0; i < 2; i++) {
            #pragma unroll
            for (int j = 0; j < 4; j++) {
                const int r = row0 + warpM + i * 16 + (lane >> 2);
                const int c = col0 + warpN + j * 8 + (lane & 3) * 2;
                #pragma unroll
                for (int half = 0; half < 2; half++) {
                    const int rr = r + half * 8;
                    const float gg0 = accG[i][j][half * 2 + 0];
                    const float gg1 = accG[i][j][half * 2 + 1];
                    const float uu0 = accU[i][j][half * 2 + 0];
                    const float uu1 = accU[i][j][half * 2 + 1];
                    __half2 hp = __halves2half2(__float2half_rn(silu(gg0) * uu0),
                                                __float2half_rn(silu(gg1) * uu1));
                    ((u32*)Hh)[((size_t)rr * INTER + c) >> 1] = *(u32*)&hp;
                }
            }
        }
    } else {
        // ======== router (fp16x3), 2-stage double buffer ========
        const int col0 = (blockIdx.y - 64) * 64;

        auto load_stage = [&](int kt, int buf) {
            const u32 so = sb + buf * STG_R;
            const size_t goA = (size_t)(row0 + lrA) * HID + kt * 32;
            cp16(so + lrA * PITCH + cA * 16,                  Xh + goA + cA * 8);
            cp16(so + lrA * PITCH + (cA + 1) * 16,            Xh + goA + (cA + 1) * 8);
            cp16(so + PLANE128 + lrA * PITCH + cA * 16,       Xl + goA + cA * 8);
            cp16(so + PLANE128 + lrA * PITCH + (cA + 1) * 16, Xl + goA + (cA + 1) * 8);
            const size_t goB = (size_t)(col0 + lrB) * HID + kt * 32;
            cp16(so + 2 * PLANE128 + lrB * PITCH + cB * 16,           Wrh + goB + cB * 8);
            cp16(so + 2 * PLANE128 + PLANE64 + lrB * PITCH + cB * 16, Wrl + goB + cB * 8);
        };

        float acc[2][4][4];
        u32   accX[2][4][2];
        #pragma unroll
        for (int i = 0; i < 2; i++)
            #pragma unroll
            for (int j = 0; j < 4; j++) {
                #pragma unroll
                for (int t = 0; t < 4; t++) acc[i][j][t] = 0.f;
                accX[i][j][0] = 0u; accX[i][j][1] = 0u;
            }

        load_stage(0, 0); CP_COMMIT();

        for (int s = 0; s < NS; s++) {
            const int buf = s & 1;
            if (s + 1 < NS) load_stage(s + 1, (s + 1) & 1);
            CP_COMMIT();
            CP_WAIT(1);
            __syncthreads();

            const u32 stg = sb + buf * STG_R;
            #pragma unroll
            for (int ks = 0; ks < 2; ks++) {
                const u32 kb = ks * 32;
                u32 ah[2][4], al[2][4], bh[4][2], bl[4][2];
                #pragma unroll
                for (int i = 0; i < 2; i++) {
                    const u32 ra = stg + (warpM + i * 16) * PITCH + kb + aRowOff;
                    ldsm_x4(ah[i][0], ah[i][1], ah[i][2], ah[i][3], ra);
                    ldsm_x4(al[i][0], al[i][1], al[i][2], al[i][3], ra + PLANE128);
                }
                #pragma unroll
                for (int j = 0; j < 4; j++) {
                    const u32 rb = stg + 2 * PLANE128 + (warpN + j * 8) * PITCH + kb + bRowOff;
                    ldsm_x2(bh[j][0], bh[j][1], rb);
                    ldsm_x2(bl[j][0], bl[j][1], rb + PLANE64);
                }
                #pragma unroll
                for (int i = 0; i < 2; i++)
                    #pragma unroll
                    for (int j = 0; j < 4; j++) {
                        mma_f32(acc[i][j], ah[i], bh[j]);
                        mma_f16(accX[i][j], ah[i], bl[j]);
                        mma_f16(accX[i][j], al[i], bh[j]);
                    }
            }
            __syncthreads();
        }

        #pragma unroll
        for (int i = 0; i < 2; i++) {
            #pragma unroll
            for (int j = 0; j < 4; j++) {
                float2 x0 = __half22float2(*(__half2*)&accX[i][j][0]);
                float2 x1 = __half22float2(*(__half2*)&accX[i][j][1]);
                const float vv[4] = { acc[i][j][0] + x0.x, acc[i][j][1] + x0.y,
                                      acc[i][j][2] + x1.x, acc[i][j][3] + x1.y };
                const int r = row0 + warpM + i * 16 + (lane >> 2);
                const int c = col0 + warpN + j * 8 + (lane & 3) * 2;
                #pragma unroll
                for (int half = 0; half < 2; half++) {
                    const int rr = r + half * 8;
                    *(float2*)(logits + (size_t)rr * 128 + c) =
                        make_float2(vv[half * 2 + 0], vv[half * 2 + 1]);
                }
            }
        }
    }
}

// =====================================================================
// down GEMM: out += H @ Wd^T. Tile 128x128, 4-stage, occ 2.
// =====================================================================
#define STG1 20480                    // 2 x PLANE128

__global__ __launch_bounds__(256, 2)
void down_kernel(const u16* __restrict__ A_h, const u16* __restrict__ B_h,
                 int K, float* __restrict__ C, int ldC)
{
    extern __shared__ char sm[];
    const u32 sb = smem_u32(sm);
    const int tid  = threadIdx.x;
    const int lane = tid & 31;
    const int wid  = tid >> 5;
    const int row0 = blockIdx.x * 128;
    const int col0 = blockIdx.y * 128;
    const int warpM = (wid >> 2) * 64;
    const int warpN = (wid & 3) * 32;

    const int f  = tid * 2;
    const int lr = f >> 2;
    const int c0 = f & 3;

    const int NS = K >> 5;

    auto load_stage = [&](int kt, int buf) {
        const size_t goA = (size_t)(row0 + lr) * K + kt * 32;
        const size_t goB = (size_t)(col0 + lr) * K + kt * 32;
        const u32 so = sb + buf * STG1 + lr * PITCH;
        cp16(so + c0 * 16,                  A_h + goA + c0 * 8);
        cp16(so + (c0 + 1) * 16,            A_h + goA + (c0 + 1) * 8);
        cp16(so + PLANE128 + c0 * 16,       B_h + goB + c0 * 8);
        cp16(so + PLANE128 + (c0 + 1) * 16, B_h + goB + (c0 + 1) * 8);
    };

    float acc[4][4][4];
    #pragma unroll
    for (int i = 0; i < 4; i++)
        #pragma unroll
        for (int j = 0; j < 4; j++)
            #pragma unroll
            for (int t = 0; t < 4; t++) acc[i][j][t] = 0.f;

    const int l4 = lane & 15;
    const u32 aRowOff = (u32)((lane & 15) * PITCH + ((lane >> 4) << 4));
    const u32 bRowOff = (u32)((l4 & 7) * PITCH + ((l4 >> 3) << 4));

    load_stage(0, 0); CP_COMMIT();
    load_stage(1, 1); CP_COMMIT();
    load_stage(2, 2); CP_COMMIT();

    for (int s = 0; s < NS; s++) {
        const int buf = s & 3;
        CP_WAIT(2);
        __syncthreads();
        if (s + 3 < NS) load_stage(s + 3, (s + 3) & 3);
        CP_COMMIT();

        const u32 stg = sb + buf * STG1;
        #pragma unroll
        for (int ks = 0; ks < 2; ks++) {
            const u32 kb = ks * 32;
            u32 ah[4][4], bh[4][2];
            #pragma unroll
            for (int i = 0; i < 4; i++)
                ldsm_x4(ah[i][0], ah[i][1], ah[i][2], ah[i][3],
                        stg + (warpM + i * 16) * PITCH + kb + aRowOff);
            #pragma unroll
            for (int j = 0; j < 4; j++)
                ldsm_x2(bh[j][0], bh[j][1],
                        stg + PLANE128 + (warpN + j * 8) * PITCH + kb + bRowOff);
            #pragma unroll
            for (int i = 0; i < 4; i++)
                #pragma unroll
                for (int j = 0; j < 4; j++) mma_f32(acc[i][j], ah[i], bh[j]);
        }
    }

    #pragma unroll
    for (int i = 0; i < 4; i++) {
        #pragma unroll
        for (int j = 0; j < 4; j++) {
            const int r = row0 + warpM + i * 16 + (lane >> 2);
            const int c = col0 + warpN + j * 8 + (lane & 3) * 2;
            #pragma unroll
            for (int half = 0; half < 2; half++) {
                const int rr = r + half * 8;
                float2 prev = *(const float2*)(C + (size_t)rr * ldC + c);
                *(float2*)(C + (size_t)rr * ldC + c) =
                    make_float2(prev.x + acc[i][j][half * 2 + 0],
                                prev.y + acc[i][j][half * 2 + 1]);
            }
        }
    }
}

// ---------------- routing ----------------
__device__ __forceinline__ void top8_insert(float v, int idx, float* hv, int* hi) {
    if (v <= hv[7]) return;
    int p = 7;
    #pragma unroll
    for (int q = 7; q > 0; q--) {
        if (v > hv[q-1]) { hv[q] = hv[q-1]; hi[q] = hi[q-1]; p = q - 1; }
    }
    hv[p] = v; hi[p] = idx;
}

__global__ void routing_kernel(const float* __restrict__ logits)
{
    int m = blockIdx.x * blockDim.x + threadIdx.x;
    if (m >= NTOK) return;

    const float* px = logits + (size_t)(m >> 1) * 128 + (m & 1) * 64;
    const float* py = logits + (size_t)(2048 + (m >> 1)) * 128 + (m & 1) * 64;

    float vx[8], vy[8];
    int   ix[8], iy[8];
    #pragma unroll
    for (int t = 0; t < 8; t++) { vx[t] = -3.4e38f; vy[t] = -3.4e38f; ix[t] = 0; iy[t] = 0; }
    for (int k = 0; k < NKEYS; k++) top8_insert(px[k], k, vx, ix);
    for (int k = 0; k < NKEYS; k++) top8_insert(py[k], k, vy, iy);

    float sv[8]; int sa[8];
    #pragma unroll
    for (int t = 0; t < 8; t++) { sv[t] = -3.4e38f; sa[t] = 0; }
    for (int a = 0; a < 8; a++)
        for (int b = 0; b < 8; b++)
            top8_insert(vx[a] + vy[b], a * 8 + b, sv, sa);

    float mx = sv[0];
    float e[8], s = 0.f;
    #pragma unroll
    for (int t = 0; t < 8; t++) { e[t] = expf(sv[t] - mx); s += e[t]; }
    float w[8], s2 = 0.f;
    #pragma unroll
    for (int t = 0; t < 8; t++) { w[t] = e[t] / s; s2 += w[t]; }
    #pragma unroll
    for (int t = 0; t < 8; t++) w[t] /= s2;

    #pragma unroll
    for (int t = 0; t < 8; t++) {
        int a = sa[t] >> 3, b = sa[t] & 7;
        g_tidx[m * TOPK + t] = ix[a] * NKEYS + iy[b];
        g_tw[m * TOPK + t]   = w[t];
    }
}

// ---------------- experts ----------------
__global__ __launch_bounds__(256)
void experts_kernel(const float* __restrict__ X,
                    const float* __restrict__ down_e,
                    const float* __restrict__ up_e,
                    float* __restrict__ out)
{
    __shared__ float4 xs4[HID / 4];
    __shared__ float  ews[TOPK];

    const int m   = blockIdx.x;
    const int tid = threadIdx.x;

    xs4[tid] = ((const float4*)(X + (size_t)m * HID))[tid];
    __syncthreads();

    const float* xs = (const float*)xs4;
    const int wid  = tid >> 5;
    const int lane = tid & 31;

    {
        int e = g_tidx[m * TOPK + wid];
        const float* d = down_e + (size_t)e * HID;
        float s = 0.f;
        for (int k = lane; k < HID; k += 32) s = fmaf(d[k], xs[k], s);
        #pragma unroll
        for (int o = 16; o; o >>= 1) s += __shfl_xor_sync(0xffffffffu, s, o);
        if (lane == 0) {
            float sig = s / (1.f + expf(-s));
            ews[wid] = sig * g_tw[m * TOPK + wid];
        }
    }
    __syncthreads();

    float4 acc = make_float4(0.f, 0.f, 0.f, 0.f);
    #pragma unroll
    for (int k = 0; k < TOPK; k++) {
        int e = g_tidx[m * TOPK + k];
        float w = ews[k];
        float4 u = ((const float4*)(up_e + (size_t)e * HID))[tid];
        acc.x = fmaf(w, u.x, acc.x);
        acc.y = fmaf(w, u.y, acc.y);
        acc.z = fmaf(w, u.z, acc.z);
        acc.w = fmaf(w, u.w, acc.w);
    }
    ((float4*)(out + (size_t)m * HID))[tid] = acc;
}

// ---------------- launch ----------------
static void* sym(const void* s) { void* p = nullptr; cudaGetSymbolAddress(&p, s); return p; }

extern "C" void kernel_launch(void* const* d_in, const int* in_sizes, int n_in,
                              void* d_out, int out_size)
{
    const float* X        = (const float*)d_in[0];
    const float* w_gate   = (const float*)d_in[1];
    const float* w_up     = (const float*)d_in[2];
    const float* w_down   = (const float*)d_in[3];
    const float* w_router = (const float*)d_in[4];
    const float* down_e   = (const float*)d_in[5];
    const float* up_e     = (const float*)d_in[6];

    float* out    = (float*)d_out;
    float* logits = (float*)d_out + (size_t)NTOK * HID;

    u16 *Xh = (u16*)sym(g_Xh),  *Xl = (u16*)sym(g_Xl);
    u16 *Wgh = (u16*)sym(g_Wgh);
    u16 *Wuh = (u16*)sym(g_Wuh);
    u16 *Wdh = (u16*)sym(g_Wdh);
    u16 *Wrh = (u16*)sym(g_Wrh), *Wrl = (u16*)sym(g_Wrl);
    u16 *Hh = (u16*)sym(g_Hh);

    const int SMEM_DOWN = 4 * STG1;   // 81920
    cudaFuncSetAttribute(mlp1_kernel, cudaFuncAttributeMaxDynamicSharedMemorySize, SMEM_MLP1);
    cudaFuncSetAttribute(down_kernel, cudaFuncAttributeMaxDynamicSharedMemorySize, SMEM_DOWN);

    // 0) splits
    {
        int n4 = NTOK * HID / 4;
        split2_kernel<<<(n4 + 255) / 256, 256>>>(X, Xh, Xl, n4);
        int r4 = 128 * HID / 4;
        split2_kernel<<<(r4 + 255) / 256, 256>>>(w_router, Wrh, Wrl, r4);
        int w4 = INTER * HID / 4;
        split1x3_kernel<<<dim3((w4 + 255) / 256, 3), 256>>>(w_gate, Wgh, w_up, Wuh,
                                                            w_down, Wdh, w4);
    }
    // 1) fused gate/up + router
    mlp1_kernel<<<dim3(NTOK / 128, 66), 256, SMEM_MLP1>>>(
        Xh, Xl, Wgh, Wuh, Wrh, Wrl, Hh, logits);
    // 2) routing top-k
    routing_kernel<<<NTOK / 256, 256>>>(logits);
    // 3) expert states -> out (initializes it)
    experts_kernel<<<NTOK, 256>>>(X, down_e, up_e, out);
    // 4) out += H @ Wd^T
    down_kernel<<<dim3(NTOK / 128, HID / 128), 256, SMEM_DOWN>>>(Hh, Wdh, INTER, out, HID);
    (void)in_sizes; (void)n_in; (void)out_size;
}

// round 8
// speedup vs baseline: 5.1289x; 1.0455x over previous
#include <cuda_runtime.h>
#include <cuda_fp16.h>
#include <cstdint>
#include <math.h>

#define HID    1024
#define INTER  4096
#define NTOK   4096
#define NKEYS  64
#define TOPK   8

typedef unsigned short u16;
typedef unsigned int   u32;

// ---------------- scratch (no allocations allowed) ----------------
__device__ __align__(16) static u16   g_Xh[(size_t)NTOK * HID];
__device__ __align__(16) static u16   g_Xl[(size_t)NTOK * HID];
__device__ __align__(16) static u16   g_Wgh[(size_t)INTER * HID];
__device__ __align__(16) static u16   g_Wuh[(size_t)INTER * HID];
__device__ __align__(16) static u16   g_Wdh[(size_t)HID * INTER];
__device__ __align__(16) static u16   g_Wrh[(size_t)128 * HID];
__device__ __align__(16) static u16   g_Wrl[(size_t)128 * HID];
__device__ __align__(16) static u16   g_Hh[(size_t)NTOK * INTER];
__device__ static int   g_tidx[NTOK * TOPK];
__device__ static float g_tw[NTOK * TOPK];

// ---------------- helpers ----------------
__device__ __forceinline__ u32 smem_u32(const void* p) {
    u32 a;
    asm("{ .reg .u64 t; cvta.to.shared.u64 t, %1; cvt.u32.u64 %0, t; }" : "=r"(a) : "l"(p));
    return a;
}

__device__ __forceinline__ void cp16(u32 dst, const void* src) {
    asm volatile("cp.async.cg.shared.global [%0], [%1], 16;" :: "r"(dst), "l"(src));
}
#define CP_COMMIT() asm volatile("cp.async.commit_group;" ::: "memory")
#define CP_WAIT(n)  asm volatile("cp.async.wait_group %0;" :: "n"(n) : "memory")

__device__ __forceinline__ void ldsm_x4(u32& r0, u32& r1, u32& r2, u32& r3, u32 addr) {
    asm volatile("ldmatrix.sync.aligned.m8n8.x4.shared.b16 {%0,%1,%2,%3}, [%4];"
                 : "=r"(r0), "=r"(r1), "=r"(r2), "=r"(r3) : "r"(addr));
}
__device__ __forceinline__ void ldsm_x2(u32& r0, u32& r1, u32 addr) {
    asm volatile("ldmatrix.sync.aligned.m8n8.x2.shared.b16 {%0,%1}, [%2];"
                 : "=r"(r0), "=r"(r1) : "r"(addr));
}

__device__ __forceinline__ void mma_f32(float* c, const u32* a, const u32* b) {
    asm volatile(
        "mma.sync.aligned.m16n8k16.row.col.f32.f16.f16.f32 "
        "{%0,%1,%2,%3}, {%4,%5,%6,%7}, {%8,%9}, {%0,%1,%2,%3};"
        : "+f"(c[0]), "+f"(c[1]), "+f"(c[2]), "+f"(c[3])
        : "r"(a[0]), "r"(a[1]), "r"(a[2]), "r"(a[3]), "r"(b[0]), "r"(b[1]));
}
__device__ __forceinline__ void mma_f16(u32* c, const u32* a, const u32* b) {
    asm volatile(
        "mma.sync.aligned.m16n8k16.row.col.f16.f16.f16.f16 "
        "{%0,%1}, {%2,%3,%4,%5}, {%6,%7}, {%0,%1};"
        : "+r"(c[0]), "+r"(c[1])
        : "r"(a[0]), "r"(a[1]), "r"(a[2]), "r"(a[3]), "r"(b[0]), "r"(b[1]));
}

__device__ __forceinline__ float silu(float x) { return x / (1.f + expf(-x)); }

// =====================================================================
// fused split kernel: all fp32->fp16 conversions in one launch.
// blocks [0,4096): X split2 ; [4096,4224): Wr split2 ;
// [4224,8320): Wg ; [8320,12416): Wu ; [12416,16512): Wd (split1)
// =====================================================================
__global__ void split_all_kernel(const float* __restrict__ X,
                                 const float* __restrict__ Wr,
                                 const float* __restrict__ Wg,
                                 const float* __restrict__ Wu,
                                 const float* __restrict__ Wd,
                                 u16* __restrict__ Xh, u16* __restrict__ Xl,
                                 u16* __restrict__ Wrh, u16* __restrict__ Wrl,
                                 u16* __restrict__ Wgh, u16* __restrict__ Wuh,
                                 u16* __restrict__ Wdh)
{
    const int b = blockIdx.x;
    const int tid = threadIdx.x;
    if (b < 4224) {
        // split2 path
        const float* src; u16 *hi, *lo; int i;
        if (b < 4096) { src = X;  hi = Xh;  lo = Xl;  i = b * 256 + tid; }
        else          { src = Wr; hi = Wrh; lo = Wrl; i = (b - 4096) * 256 + tid; }
        float4 v = ((const float4*)src)[i];
        __half hx = __float2half_rn(v.x), hy = __float2half_rn(v.y);
        __half hz = __float2half_rn(v.z), hw = __float2half_rn(v.w);
        __half lx = __float2half_rn(v.x - __half2float(hx));
        __half ly = __float2half_rn(v.y - __half2float(hy));
        __half lz = __float2half_rn(v.z - __half2float(hz));
        __half lw = __float2half_rn(v.w - __half2float(hw));
        __half2 h0 = __halves2half2(hx, hy), h1 = __halves2half2(hz, hw);
        __half2 l0 = __halves2half2(lx, ly), l1 = __halves2half2(lz, lw);
        ((uint2*)hi)[i] = make_uint2(*(u32*)&h0, *(u32*)&h1);
        ((uint2*)lo)[i] = make_uint2(*(u32*)&l0, *(u32*)&l1);
    } else {
        const float* src; u16* dst; int i;
        if (b < 8320)       { src = Wg; dst = Wgh; i = (b - 4224) * 256 + tid; }
        else if (b < 12416) { src = Wu; dst = Wuh; i = (b - 8320) * 256 + tid; }
        else                { src = Wd; dst = Wdh; i = (b - 12416) * 256 + tid; }
        float4 v = ((const float4*)src)[i];
        __half2 h0 = __halves2half2(__float2half_rn(v.x), __float2half_rn(v.y));
        __half2 h1 = __halves2half2(__float2half_rn(v.z), __float2half_rn(v.w));
        ((uint2*)dst)[i] = make_uint2(*(u32*)&h0, *(u32*)&h1);
    }
}

#define PITCH 80
#define PLANE128 10240                // 128 rows * 80
#define PLANE64  5120                 // 64 rows * 80

// =====================================================================
// mlp1_kernel: grid (32, 66), 256 thr, occ 2. CTA tile 128(M)x64(N).
//  y < 64 : fused gate/up — Hh = f16(silu(X@Wg^T) * (X@Wu^T))
//  y >= 64: router (fp16x3) — logits columns [(y-64)*64 .. +64)
// =====================================================================
#define STG_GU 20480
#define STG_R  30720
#define SMEM_MLP1 61440

__global__ __launch_bounds__(256, 2)
void mlp1_kernel(const u16* __restrict__ Xh, const u16* __restrict__ Xl,
                 const u16* __restrict__ Wgh, const u16* __restrict__ Wuh,
                 const u16* __restrict__ Wrh, const u16* __restrict__ Wrl,
                 u16* __restrict__ Hh, float* __restrict__ logits)
{
    extern __shared__ char sm[];
    const u32 sb = smem_u32(sm);
    const int tid  = threadIdx.x;
    const int lane = tid & 31;
    const int wid  = tid >> 5;
    const int row0 = blockIdx.x * 128;
    const int warpM = (wid & 3) * 32;
    const int warpN = (wid >> 2) * 32;

    const int lrA = tid >> 1;
    const int cA  = (tid & 1) * 2;
    const int lrB = tid >> 2;
    const int cB  = tid & 3;

    const int l4 = lane & 15;
    const u32 aRowOff = (u32)((lane & 15) * PITCH + ((lane >> 4) << 4));
    const u32 bRowOff = (u32)((l4 & 7) * PITCH + ((l4 >> 3) << 4));

    const int NS = HID >> 5;

    if (blockIdx.y < 64) {
        const int col0 = blockIdx.y * 64;

        auto load_stage = [&](int kt, int buf) {
            const u32 so = sb + buf * STG_GU;
            const size_t goA = (size_t)(row0 + lrA) * HID + kt * 32;
            cp16(so + lrA * PITCH + cA * 16,       Xh + goA + cA * 8);
            cp16(so + lrA * PITCH + (cA + 1) * 16, Xh + goA + (cA + 1) * 8);
            const size_t goB = (size_t)(col0 + lrB) * HID + kt * 32;
            cp16(so + PLANE128 + lrB * PITCH + cB * 16,            Wgh + goB + cB * 8);
            cp16(so + PLANE128 + PLANE64 + lrB * PITCH + cB * 16,  Wuh + goB + cB * 8);
        };

        float accG[2][4][4], accU[2][4][4];
        #pragma unroll
        for (int i = 0; i < 2; i++)
            #pragma unroll
            for (int j = 0; j < 4; j++)
                #pragma unroll
                for (int t = 0; t < 4; t++) { accG[i][j][t] = 0.f; accU[i][j][t] = 0.f; }

        load_stage(0, 0); CP_COMMIT();
        load_stage(1, 1); CP_COMMIT();

        for (int s = 0; s < NS; s++) {
            const int buf = s % 3;
            CP_WAIT(1);
            __syncthreads();
            if (s + 2 < NS) load_stage(s + 2, (s + 2) % 3);
            CP_COMMIT();

            const u32 stg = sb + buf * STG_GU;
            #pragma unroll
            for (int ks = 0; ks < 2; ks++) {
                const u32 kb = ks * 32;
                u32 ah[2][4], bg[4][2], bu[4][2];
                #pragma unroll
                for (int i = 0; i < 2; i++)
                    ldsm_x4(ah[i][0], ah[i][1], ah[i][2], ah[i][3],
                            stg + (warpM + i * 16) * PITCH + kb + aRowOff);
                #pragma unroll
                for (int j = 0; j < 4; j++) {
                    const u32 rb = stg + PLANE128 + (warpN + j * 8) * PITCH + kb + bRowOff;
                    ldsm_x2(bg[j][0], bg[j][1], rb);
                    ldsm_x2(bu[j][0], bu[j][1], rb + PLANE64);
                }
                #pragma unroll
                for (int i = 0; i < 2; i++)
                    #pragma unroll
                    for (int j = 0; j < 4; j++) {
                        mma_f32(accG[i][j], ah[i], bg[j]);
                        mma_f32(accU[i][j], ah[i], bu[j]);
                    }
            }
        }

        #pragma unroll
        for (int i = 0; i < 2; i++) {
            #pragma unroll
            for (int j = 0; j < 4; j++) {
                const int r = row0 + warpM + i * 16 + (lane >> 2);
                const int c = col0 + warpN + j * 8 + (lane & 3) * 2;
                #pragma unroll
                for (int half = 0; half < 2; half++) {
                    const int rr = r + half * 8;
                    const float gg0 = accG[i][j][half * 2 + 0];
                    const float gg1 = accG[i][j][half * 2 + 1];
                    const float uu0 = accU[i][j][half * 2 + 0];
                    const float uu1 = accU[i][j][half * 2 + 1];
                    __half2 hp = __halves2half2(__float2half_rn(silu(gg0) * uu0),
                                                __float2half_rn(silu(gg1) * uu1));
                    ((u32*)Hh)[((size_t)rr * INTER + c) >> 1] = *(u32*)&hp;
                }
            }
        }
    } else {
        const int col0 = (blockIdx.y - 64) * 64;

        auto load_stage = [&](int kt, int buf) {
            const u32 so = sb + buf * STG_R;
            const size_t goA = (size_t)(row0 + lrA) * HID + kt * 32;
            cp16(so + lrA * PITCH + cA * 16,                  Xh + goA + cA * 8);
            cp16(so + lrA * PITCH + (cA + 1) * 16,            Xh + goA + (cA + 1) * 8);
            cp16(so + PLANE128 + lrA * PITCH + cA * 16,       Xl + goA + cA * 8);
            cp16(so + PLANE128 + lrA * PITCH + (cA + 1) * 16, Xl + goA + (cA + 1) * 8);
            const size_t goB = (size_t)(col0 + lrB) * HID + kt * 32;
            cp16(so + 2 * PLANE128 + lrB * PITCH + cB * 16,           Wrh + goB + cB * 8);
            cp16(so + 2 * PLANE128 + PLANE64 + lrB * PITCH + cB * 16, Wrl + goB + cB * 8);
        };

        float acc[2][4][4];
        u32   accX[2][4][2];
        #pragma unroll
        for (int i = 0; i < 2; i++)
            #pragma unroll
            for (int j = 0; j < 4; j++) {
                #pragma unroll
                for (int t = 0; t < 4; t++) acc[i][j][t] = 0.f;
                accX[i][j][0] = 0u; accX[i][j][1] = 0u;
            }

        load_stage(0, 0); CP_COMMIT();

        for (int s = 0; s < NS; s++) {
            const int buf = s & 1;
            if (s + 1 < NS) load_stage(s + 1, (s + 1) & 1);
            CP_COMMIT();
            CP_WAIT(1);
            __syncthreads();

            const u32 stg = sb + buf * STG_R;
            #pragma unroll
            for (int ks = 0; ks < 2; ks++) {
                const u32 kb = ks * 32;
                u32 ah[2][4], al[2][4], bh[4][2], bl[4][2];
                #pragma unroll
                for (int i = 0; i < 2; i++) {
                    const u32 ra = stg + (warpM + i * 16) * PITCH + kb + aRowOff;
                    ldsm_x4(ah[i][0], ah[i][1], ah[i][2], ah[i][3], ra);
                    ldsm_x4(al[i][0], al[i][1], al[i][2], al[i][3], ra + PLANE128);
                }
                #pragma unroll
                for (int j = 0; j < 4; j++) {
                    const u32 rb = stg + 2 * PLANE128 + (warpN + j * 8) * PITCH + kb + bRowOff;
                    ldsm_x2(bh[j][0], bh[j][1], rb);
                    ldsm_x2(bl[j][0], bl[j][1], rb + PLANE64);
                }
                #pragma unroll
                for (int i = 0; i < 2; i++)
                    #pragma unroll
                    for (int j = 0; j < 4; j++) {
                        mma_f32(acc[i][j], ah[i], bh[j]);
                        mma_f16(accX[i][j], ah[i], bl[j]);
                        mma_f16(accX[i][j], al[i], bh[j]);
                    }
            }
            __syncthreads();
        }

        #pragma unroll
        for (int i = 0; i < 2; i++) {
            #pragma unroll
            for (int j = 0; j < 4; j++) {
                float2 x0 = __half22float2(*(__half2*)&accX[i][j][0]);
                float2 x1 = __half22float2(*(__half2*)&accX[i][j][1]);
                const float vv[4] = { acc[i][j][0] + x0.x, acc[i][j][1] + x0.y,
                                      acc[i][j][2] + x1.x, acc[i][j][3] + x1.y };
                const int r = row0 + warpM + i * 16 + (lane >> 2);
                const int c = col0 + warpN + j * 8 + (lane & 3) * 2;
                #pragma unroll
                for (int half = 0; half < 2; half++) {
                    const int rr = r + half * 8;
                    *(float2*)(logits + (size_t)rr * 128 + c) =
                        make_float2(vv[half * 2 + 0], vv[half * 2 + 1]);
                }
            }
        }
    }
}

// =====================================================================
// routing_zero_kernel: grid 4096. Every block zeros its 4KB slice of out;
// blocks [0,16) also compute routing for tokens [b*256, b*256+256).
// =====================================================================
__device__ __forceinline__ void top8_insert(float v, int idx, float* hv, int* hi) {
    if (v <= hv[7]) return;
    int p = 7;
    #pragma unroll
    for (int q = 7; q > 0; q--) {
        if (v > hv[q-1]) { hv[q] = hv[q-1]; hi[q] = hi[q-1]; p = q - 1; }
    }
    hv[p] = v; hi[p] = idx;
}

__global__ void routing_zero_kernel(const float* __restrict__ logits,
                                    float* __restrict__ out)
{
    const int b = blockIdx.x;
    const int tid = threadIdx.x;
    ((float4*)out)[b * 256 + tid] = make_float4(0.f, 0.f, 0.f, 0.f);
    if (b >= 16) return;

    const int m = b * 256 + tid;
    const float* px = logits + (size_t)(m >> 1) * 128 + (m & 1) * 64;
    const float* py = logits + (size_t)(2048 + (m >> 1)) * 128 + (m & 1) * 64;

    float vx[8], vy[8];
    int   ix[8], iy[8];
    #pragma unroll
    for (int t = 0; t < 8; t++) { vx[t] = -3.4e38f; vy[t] = -3.4e38f; ix[t] = 0; iy[t] = 0; }
    for (int k = 0; k < NKEYS; k++) top8_insert(px[k], k, vx, ix);
    for (int k = 0; k < NKEYS; k++) top8_insert(py[k], k, vy, iy);

    float sv[8]; int sa[8];
    #pragma unroll
    for (int t = 0; t < 8; t++) { sv[t] = -3.4e38f; sa[t] = 0; }
    for (int a = 0; a < 8; a++)
        for (int bq = 0; bq < 8; bq++)
            top8_insert(vx[a] + vy[bq], a * 8 + bq, sv, sa);

    float mx = sv[0];
    float e[8], s = 0.f;
    #pragma unroll
    for (int t = 0; t < 8; t++) { e[t] = expf(sv[t] - mx); s += e[t]; }
    float w[8], s2 = 0.f;
    #pragma unroll
    for (int t = 0; t < 8; t++) { w[t] = e[t] / s; s2 += w[t]; }
    #pragma unroll
    for (int t = 0; t < 8; t++) w[t] /= s2;

    #pragma unroll
    for (int t = 0; t < 8; t++) {
        int a = sa[t] >> 3, bq = sa[t] & 7;
        g_tidx[m * TOPK + t] = ix[a] * NKEYS + iy[bq];
        g_tw[m * TOPK + t]   = w[t];
    }
}

// =====================================================================
// tail_kernel: one launch, grid 256+4096.
//  bid < 256 : down GEMM tile (128x128, 4-stage, atomicAdd epilogue)
//  bid >= 256: experts token (atomicAdd epilogue)
// out must be pre-zeroed; each element gets EXACTLY two atomic adds
// (one down, one experts) -> bitwise deterministic (fp add commutative).
// =====================================================================
#define STG1 20480                    // 2 x PLANE128
#define SMEM_TAIL (4 * STG1)          // 81920

__global__ __launch_bounds__(256, 2)
void tail_kernel(const u16* __restrict__ A_h, const u16* __restrict__ B_h,
                 float* __restrict__ out,
                 const float* __restrict__ X,
                 const float* __restrict__ down_e,
                 const float* __restrict__ up_e)
{
    extern __shared__ char sm[];
    const int tid  = threadIdx.x;

    if (blockIdx.x < 256) {
        // ---------------- down GEMM tile ----------------
        const u32 sb = smem_u32(sm);
        const int lane = tid & 31;
        const int wid  = tid >> 5;
        const int row0 = (blockIdx.x & 31) * 128;
        const int col0 = (blockIdx.x >> 5) * 128;
        const int warpM = (wid >> 2) * 64;
        const int warpN = (wid & 3) * 32;
        const int K = INTER, ldC = HID;

        const int f  = tid * 2;
        const int lr = f >> 2;
        const int c0 = f & 3;

        const int NS = K >> 5;

        auto load_stage = [&](int kt, int buf) {
            const size_t goA = (size_t)(row0 + lr) * K + kt * 32;
            const size_t goB = (size_t)(col0 + lr) * K + kt * 32;
            const u32 so = sb + buf * STG1 + lr * PITCH;
            cp16(so + c0 * 16,                  A_h + goA + c0 * 8);
            cp16(so + (c0 + 1) * 16,            A_h + goA + (c0 + 1) * 8);
            cp16(so + PLANE128 + c0 * 16,       B_h + goB + c0 * 8);
            cp16(so + PLANE128 + (c0 + 1) * 16, B_h + goB + (c0 + 1) * 8);
        };

        float acc[4][4][4];
        #pragma unroll
        for (int i = 0; i < 4; i++)
            #pragma unroll
            for (int j = 0; j < 4; j++)
                #pragma unroll
                for (int t = 0; t < 4; t++) acc[i][j][t] = 0.f;

        const int l4 = lane & 15;
        const u32 aRowOff = (u32)((lane & 15) * PITCH + ((lane >> 4) << 4));
        const u32 bRowOff = (u32)((l4 & 7) * PITCH + ((l4 >> 3) << 4));

        load_stage(0, 0); CP_COMMIT();
        load_stage(1, 1); CP_COMMIT();
        load_stage(2, 2); CP_COMMIT();

        for (int s = 0; s < NS; s++) {
            const int buf = s & 3;
            CP_WAIT(2);
            __syncthreads();
            if (s + 3 < NS) load_stage(s + 3, (s + 3) & 3);
            CP_COMMIT();

            const u32 stg = sb + buf * STG1;
            #pragma unroll
            for (int ks = 0; ks < 2; ks++) {
                const u32 kb = ks * 32;
                u32 ah[4][4], bh[4][2];
                #pragma unroll
                for (int i = 0; i < 4; i++)
                    ldsm_x4(ah[i][0], ah[i][1], ah[i][2], ah[i][3],
                            stg + (warpM + i * 16) * PITCH + kb + aRowOff);
                #pragma unroll
                for (int j = 0; j < 4; j++)
                    ldsm_x2(bh[j][0], bh[j][1],
                            stg + PLANE128 + (warpN + j * 8) * PITCH + kb + bRowOff);
                #pragma unroll
                for (int i = 0; i < 4; i++)
                    #pragma unroll
                    for (int j = 0; j < 4; j++) mma_f32(acc[i][j], ah[i], bh[j]);
            }
        }

        #pragma unroll
        for (int i = 0; i < 4; i++) {
            #pragma unroll
            for (int j = 0; j < 4; j++) {
                const int r = row0 + warpM + i * 16 + (lane >> 2);
                const int c = col0 + warpN + j * 8 + (lane & 3) * 2;
                #pragma unroll
                for (int half = 0; half < 2; half++) {
                    const int rr = r + half * 8;
                    atomicAdd(out + (size_t)rr * ldC + c,     acc[i][j][half * 2 + 0]);
                    atomicAdd(out + (size_t)rr * ldC + c + 1, acc[i][j][half * 2 + 1]);
                }
            }
        }
    } else {
        // ---------------- experts token ----------------
        const int m = blockIdx.x - 256;
        float4* xs4 = (float4*)sm;
        float*  ews = (float*)(sm + 4096);

        xs4[tid] = ((const float4*)(X + (size_t)m * HID))[tid];
        __syncthreads();

        const float* xs = (const float*)xs4;
        const int wid  = tid >> 5;
        const int lane = tid & 31;

        {
            int e = g_tidx[m * TOPK + wid];
            const float* d = down_e + (size_t)e * HID;
            float s = 0.f;
            for (int k = lane; k < HID; k += 32) s = fmaf(d[k], xs[k], s);
            #pragma unroll
            for (int o = 16; o; o >>= 1) s += __shfl_xor_sync(0xffffffffu, s, o);
            if (lane == 0) {
                float sig = s / (1.f + expf(-s));
                ews[wid] = sig * g_tw[m * TOPK + wid];
            }
        }
        __syncthreads();

        float4 acc = make_float4(0.f, 0.f, 0.f, 0.f);
        #pragma unroll
        for (int k = 0; k < TOPK; k++) {
            int e = g_tidx[m * TOPK + k];
            float w = ews[k];
            float4 u = ((const float4*)(up_e + (size_t)e * HID))[tid];
            acc.x = fmaf(w, u.x, acc.x);
            acc.y = fmaf(w, u.y, acc.y);
            acc.z = fmaf(w, u.z, acc.z);
            acc.w = fmaf(w, u.w, acc.w);
        }
        float* dst = out + (size_t)m * HID + tid * 4;
        atomicAdd(dst + 0, acc.x);
        atomicAdd(dst + 1, acc.y);
        atomicAdd(dst + 2, acc.z);
        atomicAdd(dst + 3, acc.w);
    }
}

// ---------------- launch ----------------
static void* sym(const void* s) { void* p = nullptr; cudaGetSymbolAddress(&p, s); return p; }

extern "C" void kernel_launch(void* const* d_in, const int* in_sizes, int n_in,
                              void* d_out, int out_size)
{
    const float* X        = (const float*)d_in[0];
    const float* w_gate   = (const float*)d_in[1];
    const float* w_up     = (const float*)d_in[2];
    const float* w_down   = (const float*)d_in[3];
    const float* w_router = (const float*)d_in[4];
    const float* down_e   = (const float*)d_in[5];
    const float* up_e     = (const float*)d_in[6];

    float* out    = (float*)d_out;
    float* logits = (float*)d_out + (size_t)NTOK * HID;

    u16 *Xh = (u16*)sym(g_Xh),  *Xl = (u16*)sym(g_Xl);
    u16 *Wgh = (u16*)sym(g_Wgh);
    u16 *Wuh = (u16*)sym(g_Wuh);
    u16 *Wdh = (u16*)sym(g_Wdh);
    u16 *Wrh = (u16*)sym(g_Wrh), *Wrl = (u16*)sym(g_Wrl);
    u16 *Hh = (u16*)sym(g_Hh);

    cudaFuncSetAttribute(mlp1_kernel, cudaFuncAttributeMaxDynamicSharedMemorySize, SMEM_MLP1);
    cudaFuncSetAttribute(tail_kernel, cudaFuncAttributeMaxDynamicSharedMemorySize, SMEM_TAIL);

    // 0) all splits, one launch
    split_all_kernel<<<16512, 256>>>(X, w_router, w_gate, w_up, w_down,
                                     Xh, Xl, Wrh, Wrl, Wgh, Wuh, Wdh);
    // 1) fused gate/up + router
    mlp1_kernel<<<dim3(NTOK / 128, 66), 256, SMEM_MLP1>>>(
        Xh, Xl, Wgh, Wuh, Wrh, Wrl, Hh, logits);
    // 2) routing top-k + zero out
    routing_zero_kernel<<<4096, 256>>>(logits, out);
    // 3) down GEMM + experts, one launch (atomic accumulation into zeroed out)
    tail_kernel<<<256 + NTOK, 256, SMEM_TAIL>>>(Hh, Wdh, out, X, down_e, up_e);
    (void)in_sizes; (void)n_in; (void)out_size;
}